// round 10
// baseline (speedup 1.0000x reference)
#include <cuda_runtime.h>
#include <cuda_fp16.h>
#include <cstdint>
#include <cstddef>

// Problem constants
#define DIM   1024
#define BATCH 16
#define SEQL  2048
#define KCONV 3
#define MTOT  (BATCH * SEQL)   // 32768

// ---------------- scratch (static; no allocs allowed) ----------------
__device__ float  g_BCx[(size_t)MTOT * 3 * DIM];               // in_proj out (fp32)
__device__ __align__(16) __half g_yh [(size_t)MTOT * DIM];     // gated conv out (half)
__device__ __align__(16) __half g_xh [(size_t)MTOT * DIM];     // x in half
__device__ __align__(16) __half g_Wih[(size_t)3 * DIM * DIM];  // Win in half
__device__ __align__(16) __half g_Woh[(size_t)DIM * DIM];      // Wout in half

// ---------------- PTX helpers (plain sm_103 legal) ----------------
__device__ __forceinline__ void cp_async16(uint32_t dst, const void* src) {
    asm volatile("cp.async.cg.shared.global [%0], [%1], 16;" :: "r"(dst), "l"(src));
}
#define CP_COMMIT()  asm volatile("cp.async.commit_group;" ::: "memory")
#define CP_WAIT2()   asm volatile("cp.async.wait_group 2;" ::: "memory")

#define SW128(off) ((off) ^ (((off) >> 3) & 0x70))

__device__ __forceinline__ uint32_t smem_u32(const void* p) {
    uint32_t a;
    asm("{ .reg .u64 t; cvta.to.shared.u64 t, %1; cvt.u32.u64 %0, t; }" : "=r"(a) : "l"(p));
    return a;
}
__device__ __forceinline__ void ldsm_x4(uint32_t* r, uint32_t addr) {
    asm volatile("ldmatrix.sync.aligned.m8n8.x4.shared.b16 {%0,%1,%2,%3}, [%4];"
        : "=r"(r[0]), "=r"(r[1]), "=r"(r[2]), "=r"(r[3]) : "r"(addr));
}
__device__ __forceinline__ void mma_f16(float* c, const uint32_t* a, const uint32_t* b)
{
    asm volatile(
        "mma.sync.aligned.m16n8k16.row.col.f32.f16.f16.f32 "
        "{%0,%1,%2,%3}, {%4,%5,%6,%7}, {%8,%9}, {%0,%1,%2,%3};"
        : "+f"(c[0]), "+f"(c[1]), "+f"(c[2]), "+f"(c[3])
        : "r"(a[0]), "r"(a[1]), "r"(a[2]), "r"(a[3]), "r"(b[0]), "r"(b[1]));
}

// ---------------- GEMM tiling ----------------
#define BM 128
#define BN 256
#define BK 64                                   // 64 halfs = 128B rows
#define NSTAGE 3
#define A_BYTES (BM * 128)                      // 16KB
#define B_BYTES (BN * 128)                      // 32KB
#define STAGE_BYTES (A_BYTES + B_BYTES)         // 48KB
#define SMEM_DYN (1024 + NSTAGE * STAGE_BYTES)  // 148480 -> 1 CTA/SM

// fill one operand tile: nrows rows x 64 halfs (128B rows, SW128-swizzled)
__device__ __forceinline__ void fill_tile(uint32_t sbase, const __half* g, int nrows,
                                          int K, int k0, int tid)
{
    const int nch = nrows * 8;
    for (int idx = tid; idx < nch; idx += 256) {
        int row = idx >> 3;
        int c4  = idx & 7;
        const __half* src = g + (size_t)row * K + k0 + c4 * 8;
        uint32_t off = (uint32_t)(row * 128 + c4 * 16);
        cp_async16(sbase + SW128(off), src);
    }
}

// ---------------- fp16 tensor-core GEMM: C[m,n] = sum_k A[m,k]*B[n,k] + bias[n] ----------
// warp grid 2(M) x 4(N), warp tile 64x64
__global__ __launch_bounds__(256, 1)
void gemm_tc_f16(const __half* __restrict__ A,
                 const __half* __restrict__ B,
                 const float* __restrict__ bias,
                 float* __restrict__ C,
                 int M, int N, int K)
{
    extern __shared__ char smem[];
    const uint32_t sbase = smem_u32(smem);
    const int tid = threadIdx.x;
    const int bm = blockIdx.y * BM;
    const int bn = blockIdx.x * BN;

    const uint32_t tile0 = (sbase + 1023) & ~1023u;

    const __half* Ag = A + (size_t)bm * K;
    const __half* Bg = B + (size_t)bn * K;
    const int NT = K / BK;   // 16

    const int w = tid >> 5, lane = tid & 31;
    const int wm = (w >> 2) * 64;   // warp M offset (0 or 64)
    const int wn = (w & 3) * 64;    // warp N offset (0..192)

    // --- ldmatrix per-lane addressing (SW128 folded) ---
    const uint32_t a_row  = (uint32_t)(lane & 15);
    const uint32_t a_xor  = (uint32_t)((lane & 7) << 4);
    const uint32_t a_ch   = (uint32_t)((lane >> 4) * 16);
    const uint32_t b_row  = (uint32_t)((lane & 7) + ((lane >> 4) & 1) * 8);
    const uint32_t b_xor  = (uint32_t)((lane & 7) << 4);
    const uint32_t b_ch   = (uint32_t)(((lane >> 3) & 1) * 16);

    const uint32_t aBase = tile0 + (uint32_t)wm * 128 + a_row * 128;
    const uint32_t bBase = tile0 + (uint32_t)A_BYTES + (uint32_t)wn * 128 + b_row * 128;

    float acc[4][8][4];
#pragma unroll
    for (int a = 0; a < 4; a++)
#pragma unroll
        for (int b = 0; b < 8; b++)
#pragma unroll
            for (int c = 0; c < 4; c++) acc[a][b][c] = 0.0f;

    // prologue: fill all 3 stages (tiles 0..2)
#pragma unroll
    for (int p = 0; p < NSTAGE; p++) {
        uint32_t sA = tile0 + p * STAGE_BYTES;
        fill_tile(sA, Ag, BM, K, p * BK, tid);
        fill_tile(sA + A_BYTES, Bg, BN, K, p * BK, tid);
        CP_COMMIT();
    }

    int s = 0;
    for (int i = 0; i < NT; i++) {
        const uint32_t soff = (uint32_t)s * STAGE_BYTES;

        CP_WAIT2();          // tile i's group complete (2 newer in flight)
        __syncthreads();

        const uint32_t aS = aBase + soff;
        const uint32_t bS = bBase + soff;

        // compute tile i from stage s: 4 k16-steps
#pragma unroll
        for (int ks = 0; ks < 4; ks++) {
            const uint32_t kb = (uint32_t)(ks * 32);
            const uint32_t ca = (kb + a_ch) ^ a_xor;
            const uint32_t cb = (kb + b_ch) ^ b_xor;
            uint32_t afr[4][4], bfr[16];
#pragma unroll
            for (int mt = 0; mt < 4; mt++) ldsm_x4(afr[mt], aS + mt * 2048 + ca);
#pragma unroll
            for (int j = 0; j < 4; j++)  ldsm_x4(&bfr[j * 4], bS + j * 2048 + cb);
#pragma unroll
            for (int mt = 0; mt < 4; mt++)
#pragma unroll
                for (int nt = 0; nt < 8; nt++)
                    mma_f16(acc[mt][nt], afr[mt], &bfr[nt * 2]);
        }

        __syncthreads();     // all warps done reading stage s
        if (i + NSTAGE < NT) {
            const uint32_t sA = tile0 + soff;
            fill_tile(sA, Ag, BM, K, (i + NSTAGE) * BK, tid);
            fill_tile(sA + A_BYTES, Bg, BN, K, (i + NSTAGE) * BK, tid);
        }
        CP_COMMIT();         // keep group count invariant

        s++; if (s >= NSTAGE) s -= NSTAGE;
    }

    // epilogue: direct stores (float2) + fp32 bias
#pragma unroll
    for (int mt = 0; mt < 4; mt++) {
#pragma unroll
        for (int nt = 0; nt < 8; nt++) {
            int row0 = bm + wm + mt * 16 + (lane >> 2);
            int col0 = bn + wn + nt * 8 + (lane & 3) * 2;
            float b0 = __ldg(bias + col0), b1 = __ldg(bias + col0 + 1);
            float2 v0 = make_float2(acc[mt][nt][0] + b0, acc[mt][nt][1] + b1);
            float2 v1 = make_float2(acc[mt][nt][2] + b0, acc[mt][nt][3] + b1);
            *(float2*)(C + (size_t)row0 * N + col0) = v0;
            *(float2*)(C + (size_t)(row0 + 8) * N + col0) = v1;
        }
    }
}

// ---------------- elementwise fp32 -> half ----------------
__global__ __launch_bounds__(256)
void cvt_f16_kernel(const float* __restrict__ in, __half* __restrict__ out, int n4)
{
    int i = blockIdx.x * blockDim.x + threadIdx.x;
    if (i < n4) {
        float4 v = reinterpret_cast<const float4*>(in)[i];
        __half2 h01 = __floats2half2_rn(v.x, v.y);
        __half2 h23 = __floats2half2_rn(v.z, v.w);
        __half2 pk[2] = { h01, h23 };
        reinterpret_cast<uint2*>(out)[i] = *reinterpret_cast<const uint2*>(pk);
    }
}

// ---------------- gate + causal depthwise conv (K=3), half output ----------------
#define LCHUNK 128

__global__ __launch_bounds__(256)
void gate_conv_kernel(const float* __restrict__ BCx,
                      const float* __restrict__ wconv,
                      __half* __restrict__ y)
{
    const int d  = blockIdx.x * blockDim.x + threadIdx.x;
    const int b  = blockIdx.y;
    const int l0 = blockIdx.z * LCHUNK;

    const float w0 = wconv[d * KCONV + 0];
    const float w1 = wconv[d * KCONV + 1];
    const float w2 = wconv[d * KCONV + 2];

    const float* base = BCx + (size_t)b * SEQL * 3 * DIM;

    float bxm2 = 0.0f, bxm1 = 0.0f;
    if (l0 >= 2) {
        const float* r = base + (size_t)(l0 - 2) * 3 * DIM;
        bxm2 = r[d] * r[2 * DIM + d];
    }
    if (l0 >= 1) {
        const float* r = base + (size_t)(l0 - 1) * 3 * DIM;
        bxm1 = r[d] * r[2 * DIM + d];
    }

    for (int l = l0; l < l0 + LCHUNK; l++) {
        const float* r = base + (size_t)l * 3 * DIM;
        float bg = r[d];
        float cg = r[DIM + d];
        float xg = r[2 * DIM + d];
        float bx = bg * xg;
        float conv = fmaf(w0, bxm2, fmaf(w1, bxm1, w2 * bx));
        y[((size_t)b * SEQL + l) * DIM + d] = __float2half_rn(cg * conv);
        bxm2 = bxm1;
        bxm1 = bx;
    }
}

// ---------------------------------------------------------------------------
extern "C" void kernel_launch(void* const* d_in, const int* in_sizes, int n_in,
                              void* d_out, int out_size)
{
    const float* x     = (const float*)d_in[0];
    const float* Win   = (const float*)d_in[1];
    const float* bin_  = (const float*)d_in[2];
    const float* wconv = (const float*)d_in[3];
    const float* Wout  = (const float*)d_in[4];
    const float* bout  = (const float*)d_in[5];
    float* out = (float*)d_out;

    float *BCx;
    __half *yh, *xh, *Wih, *Woh;
    cudaGetSymbolAddress((void**)&BCx, g_BCx);
    cudaGetSymbolAddress((void**)&yh,  g_yh);
    cudaGetSymbolAddress((void**)&xh,  g_xh);
    cudaGetSymbolAddress((void**)&Wih, g_Wih);
    cudaGetSymbolAddress((void**)&Woh, g_Woh);

    cudaFuncSetAttribute(gemm_tc_f16, cudaFuncAttributeMaxDynamicSharedMemorySize, SMEM_DYN);

    const int M = MTOT;

    // convert inputs/weights to half
    {
        int n4 = M * DIM / 4;
        cvt_f16_kernel<<<(n4 + 255) / 256, 256>>>(x, xh, n4);
        n4 = 3 * DIM * DIM / 4;
        cvt_f16_kernel<<<(n4 + 255) / 256, 256>>>(Win, Wih, n4);
        n4 = DIM * DIM / 4;
        cvt_f16_kernel<<<(n4 + 255) / 256, 256>>>(Wout, Woh, n4);
    }

    // GEMM 1: BCx = xh @ Wih^T + bin   (M x 3072, K=1024)
    {
        dim3 grid((3 * DIM) / BN, M / BM);
        gemm_tc_f16<<<grid, 256, SMEM_DYN>>>(xh, Wih, bin_, BCx, M, 3 * DIM, DIM);
    }

    // gate + causal conv -> yh (half)
    {
        dim3 grid(DIM / 256, BATCH, SEQL / LCHUNK);
        gate_conv_kernel<<<grid, 256>>>(BCx, wconv, yh);
    }

    // GEMM 2: out = yh @ Woh^T + bout  (M x 1024, K=1024)
    {
        dim3 grid(DIM / BN, M / BM);
        gemm_tc_f16<<<grid, 256, SMEM_DYN>>>(yh, Woh, bout, out, M, DIM, DIM);
    }
}

// round 11
// speedup vs baseline: 1.0752x; 1.0752x over previous
#include <cuda_runtime.h>
#include <cuda_fp16.h>
#include <cstdint>
#include <cstddef>

// Problem constants
#define DIM   1024
#define BATCH 16
#define SEQL  2048
#define KCONV 3
#define MTOT  (BATCH * SEQL)   // 32768

// ---------------- scratch (static; no allocs allowed) ----------------
__device__ __align__(16) __half g_BCh[(size_t)MTOT * 3 * DIM]; // in_proj out (half)
__device__ __align__(16) __half g_yh [(size_t)MTOT * DIM];     // gated conv out (half)
__device__ __align__(16) __half g_xh [(size_t)MTOT * DIM];     // x in half
__device__ __align__(16) __half g_Wih[(size_t)3 * DIM * DIM];  // Win in half
__device__ __align__(16) __half g_Woh[(size_t)DIM * DIM];      // Wout in half

// ---------------- PTX helpers (plain sm_103 legal) ----------------
__device__ __forceinline__ void cp_async16(uint32_t dst, const void* src) {
    asm volatile("cp.async.cg.shared.global [%0], [%1], 16;" :: "r"(dst), "l"(src));
}
#define CP_COMMIT()  asm volatile("cp.async.commit_group;" ::: "memory")
#define CP_WAIT1()   asm volatile("cp.async.wait_group 1;" ::: "memory")

#define SW128(off) ((off) ^ (((off) >> 3) & 0x70))

__device__ __forceinline__ uint32_t smem_u32(const void* p) {
    uint32_t a;
    asm("{ .reg .u64 t; cvta.to.shared.u64 t, %1; cvt.u32.u64 %0, t; }" : "=r"(a) : "l"(p));
    return a;
}
__device__ __forceinline__ void ldsm_x4(uint32_t* r, uint32_t addr) {
    asm volatile("ldmatrix.sync.aligned.m8n8.x4.shared.b16 {%0,%1,%2,%3}, [%4];"
        : "=r"(r[0]), "=r"(r[1]), "=r"(r[2]), "=r"(r[3]) : "r"(addr));
}
__device__ __forceinline__ void mma_f16(float* c, const uint32_t* a, const uint32_t* b)
{
    asm volatile(
        "mma.sync.aligned.m16n8k16.row.col.f32.f16.f16.f32 "
        "{%0,%1,%2,%3}, {%4,%5,%6,%7}, {%8,%9}, {%0,%1,%2,%3};"
        : "+f"(c[0]), "+f"(c[1]), "+f"(c[2]), "+f"(c[3])
        : "r"(a[0]), "r"(a[1]), "r"(a[2]), "r"(a[3]), "r"(b[0]), "r"(b[1]));
}

// ---------------- GEMM tiling (R9-proven: 128x128x64, 3 stages, 2 CTAs/SM) ----------------
#define BM 128
#define BN 128
#define BK 64                                   // 64 halfs = 128B rows
#define NSTAGE 3
#define A_BYTES (BM * 128)
#define STAGE_BYTES (BM * 128 + BN * 128)       // 32KB
#define SMEM_DYN (1024 + NSTAGE * STAGE_BYTES)  // 99328 -> 2 CTAs/SM

// fill one operand tile: nrows rows x 64 halfs (128B rows, SW128-swizzled)
__device__ __forceinline__ void fill_tile(uint32_t sbase, const __half* g, int nrows,
                                          int K, int k0, int tid)
{
    const int nch = nrows * 8;
    for (int idx = tid; idx < nch; idx += 256) {
        int row = idx >> 3;
        int c4  = idx & 7;
        const __half* src = g + (size_t)row * K + k0 + c4 * 8;
        uint32_t off = (uint32_t)(row * 128 + c4 * 16);
        cp_async16(sbase + SW128(off), src);
    }
}

// ---------------- fp16 tensor-core GEMM: C[m,n] = sum_k A[m,k]*B[n,k] + bias[n] ----------
// OutT = float (fp32 store) or __half (half store). warp grid 2x4, warp tile 64x32.
template <typename OutT>
__global__ __launch_bounds__(256, 2)
void gemm_tc_f16(const __half* __restrict__ A,
                 const __half* __restrict__ B,
                 const float* __restrict__ bias,
                 OutT* __restrict__ C,
                 int M, int N, int K)
{
    extern __shared__ char smem[];
    const uint32_t sbase = smem_u32(smem);
    const int tid = threadIdx.x;
    const int bm = blockIdx.y * BM;
    const int bn = blockIdx.x * BN;

    const uint32_t tile0 = (sbase + 1023) & ~1023u;

    const __half* Ag = A + (size_t)bm * K;
    const __half* Bg = B + (size_t)bn * K;
    const int NT = K / BK;   // 16

    const int w = tid >> 5, lane = tid & 31;
    const int wm = (w >> 2) * 64;   // warp M offset (0 or 64)
    const int wn = (w & 3) * 32;    // warp N offset (0..96)

    // --- ldmatrix per-lane addressing (SW128 folded) ---
    const uint32_t a_row  = (uint32_t)(lane & 15);
    const uint32_t a_xor  = (uint32_t)((lane & 7) << 4);
    const uint32_t a_ch   = (uint32_t)((lane >> 4) * 16);
    const uint32_t b_row  = (uint32_t)((lane & 7) + ((lane >> 4) & 1) * 8);
    const uint32_t b_xor  = (uint32_t)((lane & 7) << 4);
    const uint32_t b_ch   = (uint32_t)(((lane >> 3) & 1) * 16);

    const uint32_t aBase = tile0 + (uint32_t)wm * 128 + a_row * 128;
    const uint32_t bBase = tile0 + (uint32_t)A_BYTES + (uint32_t)wn * 128 + b_row * 128;

    float acc[4][4][4];
#pragma unroll
    for (int a = 0; a < 4; a++)
#pragma unroll
        for (int b = 0; b < 4; b++)
#pragma unroll
            for (int c = 0; c < 4; c++) acc[a][b][c] = 0.0f;

    // prologue: fill stages 0,1 (tiles 0,1)
#pragma unroll
    for (int p = 0; p < 2; p++) {
        uint32_t sA = tile0 + p * STAGE_BYTES;
        fill_tile(sA, Ag, BM, K, p * BK, tid);
        fill_tile(sA + A_BYTES, Bg, BN, K, p * BK, tid);
        CP_COMMIT();
    }

    int s = 0;
    for (int i = 0; i < NT; i++) {
        const uint32_t soff = (uint32_t)s * STAGE_BYTES;

        CP_WAIT1();          // tile i's fill complete (tile i+1's may be in flight)
        __syncthreads();     // all warps done with compute of tile i-1 (stage (s+2)%3)

        // prefetch tile i+2 into stage (s+2)%3 (used by tile i-1, now free)
        if (i + 2 < NT) {
            int s2 = s + 2; if (s2 >= NSTAGE) s2 -= NSTAGE;
            uint32_t sA = tile0 + (uint32_t)s2 * STAGE_BYTES;
            fill_tile(sA, Ag, BM, K, (i + 2) * BK, tid);
            fill_tile(sA + A_BYTES, Bg, BN, K, (i + 2) * BK, tid);
        }
        CP_COMMIT();         // one group per iteration (possibly empty)

        const uint32_t aS = aBase + soff;
        const uint32_t bS = bBase + soff;

        // compute tile i from stage s: 4 k16-steps
#pragma unroll
        for (int ks = 0; ks < 4; ks++) {
            const uint32_t kb = (uint32_t)(ks * 32);
            const uint32_t ca = (kb + a_ch) ^ a_xor;
            const uint32_t cb = (kb + b_ch) ^ b_xor;
            uint32_t afr[4][4], bfr[8];
#pragma unroll
            for (int mt = 0; mt < 4; mt++) ldsm_x4(afr[mt], aS + mt * 2048 + ca);
            ldsm_x4(&bfr[0], bS + cb);
            ldsm_x4(&bfr[4], bS + 2048 + cb);
#pragma unroll
            for (int mt = 0; mt < 4; mt++)
#pragma unroll
                for (int nt = 0; nt < 4; nt++)
                    mma_f16(acc[mt][nt], afr[mt], &bfr[nt * 2]);
        }

        s++; if (s >= NSTAGE) s -= NSTAGE;
    }

    // epilogue: bias + store (fp32 or half per OutT)
#pragma unroll
    for (int mt = 0; mt < 4; mt++) {
#pragma unroll
        for (int nt = 0; nt < 4; nt++) {
            int row0 = bm + wm + mt * 16 + (lane >> 2);
            int col0 = bn + wn + nt * 8 + (lane & 3) * 2;
            float b0 = __ldg(bias + col0), b1 = __ldg(bias + col0 + 1);
            float v00 = acc[mt][nt][0] + b0, v01 = acc[mt][nt][1] + b1;
            float v10 = acc[mt][nt][2] + b0, v11 = acc[mt][nt][3] + b1;
            if (sizeof(OutT) == 4) {
                float* Cf = (float*)C;
                *(float2*)(Cf + (size_t)row0 * N + col0) = make_float2(v00, v01);
                *(float2*)(Cf + (size_t)(row0 + 8) * N + col0) = make_float2(v10, v11);
            } else {
                __half* Ch = (__half*)C;
                __half2 h0 = __floats2half2_rn(v00, v01);
                __half2 h1 = __floats2half2_rn(v10, v11);
                *(__half2*)(Ch + (size_t)row0 * N + col0) = h0;
                *(__half2*)(Ch + (size_t)(row0 + 8) * N + col0) = h1;
            }
        }
    }
}

// ---------------- elementwise fp32 -> half ----------------
__global__ __launch_bounds__(256)
void cvt_f16_kernel(const float* __restrict__ in, __half* __restrict__ out, int n4)
{
    int i = blockIdx.x * blockDim.x + threadIdx.x;
    if (i < n4) {
        float4 v = reinterpret_cast<const float4*>(in)[i];
        __half2 h01 = __floats2half2_rn(v.x, v.y);
        __half2 h23 = __floats2half2_rn(v.z, v.w);
        __half2 pk[2] = { h01, h23 };
        reinterpret_cast<uint2*>(out)[i] = *reinterpret_cast<const uint2*>(pk);
    }
}

// ---------------- gate + causal depthwise conv (K=3), half in / half out ----------------
#define LCHUNK 128

__global__ __launch_bounds__(256)
void gate_conv_kernel(const __half* __restrict__ BCx,
                      const float* __restrict__ wconv,
                      __half* __restrict__ y)
{
    const int d  = blockIdx.x * blockDim.x + threadIdx.x;
    const int b  = blockIdx.y;
    const int l0 = blockIdx.z * LCHUNK;

    const float w0 = wconv[d * KCONV + 0];
    const float w1 = wconv[d * KCONV + 1];
    const float w2 = wconv[d * KCONV + 2];

    const __half* base = BCx + (size_t)b * SEQL * 3 * DIM;

    float bxm2 = 0.0f, bxm1 = 0.0f;
    if (l0 >= 2) {
        const __half* r = base + (size_t)(l0 - 2) * 3 * DIM;
        bxm2 = __half2float(r[d]) * __half2float(r[2 * DIM + d]);
    }
    if (l0 >= 1) {
        const __half* r = base + (size_t)(l0 - 1) * 3 * DIM;
        bxm1 = __half2float(r[d]) * __half2float(r[2 * DIM + d]);
    }

    for (int l = l0; l < l0 + LCHUNK; l++) {
        const __half* r = base + (size_t)l * 3 * DIM;
        float bg = __half2float(r[d]);
        float cg = __half2float(r[DIM + d]);
        float xg = __half2float(r[2 * DIM + d]);
        float bx = bg * xg;
        float conv = fmaf(w0, bxm2, fmaf(w1, bxm1, w2 * bx));
        y[((size_t)b * SEQL + l) * DIM + d] = __float2half_rn(cg * conv);
        bxm2 = bxm1;
        bxm1 = bx;
    }
}

// ---------------------------------------------------------------------------
extern "C" void kernel_launch(void* const* d_in, const int* in_sizes, int n_in,
                              void* d_out, int out_size)
{
    const float* x     = (const float*)d_in[0];
    const float* Win   = (const float*)d_in[1];
    const float* bin_  = (const float*)d_in[2];
    const float* wconv = (const float*)d_in[3];
    const float* Wout  = (const float*)d_in[4];
    const float* bout  = (const float*)d_in[5];
    float* out = (float*)d_out;

    __half *BCh, *yh, *xh, *Wih, *Woh;
    cudaGetSymbolAddress((void**)&BCh, g_BCh);
    cudaGetSymbolAddress((void**)&yh,  g_yh);
    cudaGetSymbolAddress((void**)&xh,  g_xh);
    cudaGetSymbolAddress((void**)&Wih, g_Wih);
    cudaGetSymbolAddress((void**)&Woh, g_Woh);

    cudaFuncSetAttribute(gemm_tc_f16<__half>, cudaFuncAttributeMaxDynamicSharedMemorySize, SMEM_DYN);
    cudaFuncSetAttribute(gemm_tc_f16<float>,  cudaFuncAttributeMaxDynamicSharedMemorySize, SMEM_DYN);

    const int M = MTOT;

    // convert inputs/weights to half
    {
        int n4 = M * DIM / 4;
        cvt_f16_kernel<<<(n4 + 255) / 256, 256>>>(x, xh, n4);
        n4 = 3 * DIM * DIM / 4;
        cvt_f16_kernel<<<(n4 + 255) / 256, 256>>>(Win, Wih, n4);
        n4 = DIM * DIM / 4;
        cvt_f16_kernel<<<(n4 + 255) / 256, 256>>>(Wout, Woh, n4);
    }

    // GEMM 1: BCh = half(xh @ Wih^T + bin)   (M x 3072, K=1024)
    {
        dim3 grid((3 * DIM) / BN, M / BM);
        gemm_tc_f16<__half><<<grid, 256, SMEM_DYN>>>(xh, Wih, bin_, BCh, M, 3 * DIM, DIM);
    }

    // gate + causal conv -> yh (half)
    {
        dim3 grid(DIM / 256, BATCH, SEQL / LCHUNK);
        gate_conv_kernel<<<grid, 256>>>(BCh, wconv, yh);
    }

    // GEMM 2: out = yh @ Woh^T + bout  (M x 1024, K=1024)
    {
        dim3 grid(DIM / BN, M / BM);
        gemm_tc_f16<float><<<grid, 256, SMEM_DYN>>>(yh, Woh, bout, out, M, DIM, DIM);
    }
}

// round 13
// speedup vs baseline: 1.1076x; 1.0301x over previous
#include <cuda_runtime.h>
#include <cuda_fp16.h>
#include <cstdint>
#include <cstddef>

// Problem constants
#define DIM   1024
#define BATCH 16
#define SEQL  2048
#define KCONV 3
#define MTOT  (BATCH * SEQL)   // 32768

// ---------------- scratch (static; no allocs allowed) ----------------
__device__ __align__(16) __half g_BCh[(size_t)MTOT * 3 * DIM]; // in_proj out (half)
__device__ __align__(16) __half g_yh [(size_t)MTOT * DIM];     // gated conv out (half)
__device__ __align__(16) __half g_xh [(size_t)MTOT * DIM];     // x in half
__device__ __align__(16) __half g_Wih[(size_t)3 * DIM * DIM];  // Win in half
__device__ __align__(16) __half g_Woh[(size_t)DIM * DIM];      // Wout in half

// ---------------- PTX helpers (plain sm_103 legal) ----------------
__device__ __forceinline__ void cp_async16(uint32_t dst, const void* src) {
    asm volatile("cp.async.cg.shared.global [%0], [%1], 16;" :: "r"(dst), "l"(src));
}
// one COMPLETING arrive on mbar when this thread's prior cp.asyncs finish.
// .noinc is essential: without it the pending count is incremented first (net zero).
__device__ __forceinline__ void cp_async_mbar_arrive(uint32_t mbar) {
    asm volatile("cp.async.mbarrier.arrive.noinc.shared.b64 [%0];" :: "r"(mbar) : "memory");
}
__device__ __forceinline__ void mbar_init(uint32_t mbar, uint32_t cnt) {
    asm volatile("mbarrier.init.shared.b64 [%0], %1;" :: "r"(mbar), "r"(cnt) : "memory");
}
__device__ __forceinline__ void mbar_arrive(uint32_t mbar) {
    asm volatile("mbarrier.arrive.shared.b64 _, [%0];" :: "r"(mbar) : "memory");
}
__device__ __forceinline__ void mbar_wait(uint32_t mbar, uint32_t parity) {
    uint32_t done;
    asm volatile(
        "{\n\t.reg .pred p;\n\t"
        "mbarrier.try_wait.parity.acquire.cta.shared::cta.b64 p, [%1], %2;\n\t"
        "selp.b32 %0, 1, 0, p;\n\t}"
        : "=r"(done) : "r"(mbar), "r"(parity) : "memory");
    if (!done) {
        asm volatile(
            "{\n\t.reg .pred P1;\n\t"
            "WL_%=:\n\t"
            "mbarrier.try_wait.parity.acquire.cta.shared::cta.b64 P1, [%0], %1, 0x989680;\n\t"
            "@P1 bra.uni WD_%=;\n\t"
            "bra.uni WL_%=;\n\t"
            "WD_%=:\n\t}"
            :: "r"(mbar), "r"(parity) : "memory");
    }
}
__device__ __forceinline__ uint32_t smem_u32(const void* p) {
    uint32_t a;
    asm("{ .reg .u64 t; cvta.to.shared.u64 t, %1; cvt.u32.u64 %0, t; }" : "=r"(a) : "l"(p));
    return a;
}
__device__ __forceinline__ void ldsm_x4(uint32_t* r, uint32_t addr) {
    asm volatile("ldmatrix.sync.aligned.m8n8.x4.shared.b16 {%0,%1,%2,%3}, [%4];"
        : "=r"(r[0]), "=r"(r[1]), "=r"(r[2]), "=r"(r[3]) : "r"(addr));
}
__device__ __forceinline__ void mma_f16(float* c, const uint32_t* a, const uint32_t* b)
{
    asm volatile(
        "mma.sync.aligned.m16n8k16.row.col.f32.f16.f16.f32 "
        "{%0,%1,%2,%3}, {%4,%5,%6,%7}, {%8,%9}, {%0,%1,%2,%3};"
        : "+f"(c[0]), "+f"(c[1]), "+f"(c[2]), "+f"(c[3])
        : "r"(a[0]), "r"(a[1]), "r"(a[2]), "r"(a[3]), "r"(b[0]), "r"(b[1]));
}

#define SW128(off) ((off) ^ (((off) >> 3) & 0x70))

// ---------------- GEMM tiling (128x128x64, 3 stages, 2 CTAs/SM) ----------------
#define BM 128
#define BN 128
#define BK 64                                   // 64 halfs = 128B rows
#define NSTAGE 3
#define A_BYTES (BM * 128)
#define STAGE_BYTES (BM * 128 + BN * 128)       // 32KB
#define SMEM_DYN (1024 + NSTAGE * STAGE_BYTES)  // 99328 -> 2 CTAs/SM

// fill one operand tile: nrows rows x 64 halfs (128B rows, SW128-swizzled)
__device__ __forceinline__ void fill_tile(uint32_t sbase, const __half* g, int nrows,
                                          int K, int k0, int tid)
{
    const int nch = nrows * 8;
    for (int idx = tid; idx < nch; idx += 256) {
        int row = idx >> 3;
        int c4  = idx & 7;
        const __half* src = g + (size_t)row * K + k0 + c4 * 8;
        uint32_t off = (uint32_t)(row * 128 + c4 * 16);
        cp_async16(sbase + SW128(off), src);
    }
}

// ---------------- fp16 tensor-core GEMM: C[m,n] = sum_k A[m,k]*B[n,k] + bias[n] ----------
// mbarrier full/empty pipeline; warp grid 2x4, warp tile 64x32.
template <typename OutT>
__global__ __launch_bounds__(256, 2)
void gemm_tc_f16(const __half* __restrict__ A,
                 const __half* __restrict__ B,
                 const float* __restrict__ bias,
                 OutT* __restrict__ C,
                 int M, int N, int K)
{
    extern __shared__ char smem[];
    const uint32_t sbase = smem_u32(smem);
    const int tid = threadIdx.x;
    const int bm = blockIdx.y * BM;
    const int bn = blockIdx.x * BN;

    // control region: full[s] at +0,8,16 ; empty[s] at +24,32,40
    const uint32_t mb_full  = sbase;
    const uint32_t mb_empty = sbase + 24;

    const uint32_t tile0 = (sbase + 1023) & ~1023u;

    const __half* Ag = A + (size_t)bm * K;
    const __half* Bg = B + (size_t)bn * K;
    const int NT = K / BK;   // 16

    const int w = tid >> 5, lane = tid & 31;
    const int wm = (w >> 2) * 64;   // warp M offset (0 or 64)
    const int wn = (w & 3) * 32;    // warp N offset (0..96)

    // --- ldmatrix per-lane addressing (SW128 folded) ---
    const uint32_t a_row  = (uint32_t)(lane & 15);
    const uint32_t a_xor  = (uint32_t)((lane & 7) << 4);
    const uint32_t a_ch   = (uint32_t)((lane >> 4) * 16);
    const uint32_t b_row  = (uint32_t)((lane & 7) + ((lane >> 4) & 1) * 8);
    const uint32_t b_xor  = (uint32_t)((lane & 7) << 4);
    const uint32_t b_ch   = (uint32_t)(((lane >> 3) & 1) * 16);

    const uint32_t aBase = tile0 + (uint32_t)wm * 128 + a_row * 128;
    const uint32_t bBase = tile0 + (uint32_t)A_BYTES + (uint32_t)wn * 128 + b_row * 128;

    if (tid == 0) {
#pragma unroll
        for (int s = 0; s < NSTAGE; s++) {
            mbar_init(mb_full  + s * 8, 256);
            mbar_init(mb_empty + s * 8, 256);
        }
    }
    __syncthreads();

    float acc[4][4][4];
#pragma unroll
    for (int a = 0; a < 4; a++)
#pragma unroll
        for (int b = 0; b < 4; b++)
#pragma unroll
            for (int c = 0; c < 4; c++) acc[a][b][c] = 0.0f;

    // prologue: fill all 3 stages (tiles 0..2); one cp-gated arrive per stage
#pragma unroll
    for (int p = 0; p < NSTAGE; p++) {
        uint32_t sA = tile0 + p * STAGE_BYTES;
        fill_tile(sA, Ag, BM, K, p * BK, tid);
        fill_tile(sA + A_BYTES, Bg, BN, K, p * BK, tid);
        cp_async_mbar_arrive(mb_full + p * 8);
    }

    int s = 0, ph = 0;
    for (int i = 0; i < NT; i++) {
        const uint32_t soff = (uint32_t)s * STAGE_BYTES;

        // consumer: wait for tile i's data
        mbar_wait(mb_full + s * 8, (uint32_t)ph);

        const uint32_t aS = aBase + soff;
        const uint32_t bS = bBase + soff;

        // compute tile i: 4 k16-steps; signal stage-empty right after the LAST LDSM
#pragma unroll
        for (int ks = 0; ks < 4; ks++) {
            const uint32_t kb = (uint32_t)(ks * 32);
            const uint32_t ca = (kb + a_ch) ^ a_xor;
            const uint32_t cb = (kb + b_ch) ^ b_xor;
            uint32_t afr[4][4], bfr[8];
#pragma unroll
            for (int mt = 0; mt < 4; mt++) ldsm_x4(afr[mt], aS + mt * 2048 + ca);
            ldsm_x4(&bfr[0], bS + cb);
            ldsm_x4(&bfr[4], bS + 2048 + cb);
            if (ks == 3) mbar_arrive(mb_empty + s * 8);   // done reading stage s
#pragma unroll
            for (int mt = 0; mt < 4; mt++)
#pragma unroll
                for (int nt = 0; nt < 4; nt++)
                    mma_f16(acc[mt][nt], afr[mt], &bfr[nt * 2]);
        }

        // producer: refill stage s with tile i+3 once everyone is done reading it
        if (i + NSTAGE < NT) {
            mbar_wait(mb_empty + s * 8, (uint32_t)ph);
            uint32_t sA = tile0 + soff;
            fill_tile(sA, Ag, BM, K, (i + NSTAGE) * BK, tid);
            fill_tile(sA + A_BYTES, Bg, BN, K, (i + NSTAGE) * BK, tid);
            cp_async_mbar_arrive(mb_full + s * 8);
        }

        s++; if (s >= NSTAGE) { s = 0; ph ^= 1; }
    }

    // epilogue: bias + store (fp32 or half per OutT)
#pragma unroll
    for (int mt = 0; mt < 4; mt++) {
#pragma unroll
        for (int nt = 0; nt < 4; nt++) {
            int row0 = bm + wm + mt * 16 + (lane >> 2);
            int col0 = bn + wn + nt * 8 + (lane & 3) * 2;
            float b0 = __ldg(bias + col0), b1 = __ldg(bias + col0 + 1);
            float v00 = acc[mt][nt][0] + b0, v01 = acc[mt][nt][1] + b1;
            float v10 = acc[mt][nt][2] + b0, v11 = acc[mt][nt][3] + b1;
            if (sizeof(OutT) == 4) {
                float* Cf = (float*)C;
                *(float2*)(Cf + (size_t)row0 * N + col0) = make_float2(v00, v01);
                *(float2*)(Cf + (size_t)(row0 + 8) * N + col0) = make_float2(v10, v11);
            } else {
                __half* Ch = (__half*)C;
                *(__half2*)(Ch + (size_t)row0 * N + col0) = __floats2half2_rn(v00, v01);
                *(__half2*)(Ch + (size_t)(row0 + 8) * N + col0) = __floats2half2_rn(v10, v11);
            }
        }
    }
}

// ---------------- elementwise fp32 -> half ----------------
__global__ __launch_bounds__(256)
void cvt_f16_kernel(const float* __restrict__ in, __half* __restrict__ out, int n4)
{
    int i = blockIdx.x * blockDim.x + threadIdx.x;
    if (i < n4) {
        float4 v = reinterpret_cast<const float4*>(in)[i];
        __half2 h01 = __floats2half2_rn(v.x, v.y);
        __half2 h23 = __floats2half2_rn(v.z, v.w);
        __half2 pk[2] = { h01, h23 };
        reinterpret_cast<uint2*>(out)[i] = *reinterpret_cast<const uint2*>(pk);
    }
}

// ---------------- gate + causal depthwise conv (K=3), half in / half out ----------------
#define LCHUNK 128

__global__ __launch_bounds__(256)
void gate_conv_kernel(const __half* __restrict__ BCx,
                      const float* __restrict__ wconv,
                      __half* __restrict__ y)
{
    const int d  = blockIdx.x * blockDim.x + threadIdx.x;
    const int b  = blockIdx.y;
    const int l0 = blockIdx.z * LCHUNK;

    const float w0 = wconv[d * KCONV + 0];
    const float w1 = wconv[d * KCONV + 1];
    const float w2 = wconv[d * KCONV + 2];

    const __half* base = BCx + (size_t)b * SEQL * 3 * DIM;

    float bxm2 = 0.0f, bxm1 = 0.0f;
    if (l0 >= 2) {
        const __half* r = base + (size_t)(l0 - 2) * 3 * DIM;
        bxm2 = __half2float(r[d]) * __half2float(r[2 * DIM + d]);
    }
    if (l0 >= 1) {
        const __half* r = base + (size_t)(l0 - 1) * 3 * DIM;
        bxm1 = __half2float(r[d]) * __half2float(r[2 * DIM + d]);
    }

    for (int l = l0; l < l0 + LCHUNK; l++) {
        const __half* r = base + (size_t)l * 3 * DIM;
        float bg = __half2float(r[d]);
        float cg = __half2float(r[DIM + d]);
        float xg = __half2float(r[2 * DIM + d]);
        float bx = bg * xg;
        float conv = fmaf(w0, bxm2, fmaf(w1, bxm1, w2 * bx));
        y[((size_t)b * SEQL + l) * DIM + d] = __float2half_rn(cg * conv);
        bxm2 = bxm1;
        bxm1 = bx;
    }
}

// ---------------------------------------------------------------------------
extern "C" void kernel_launch(void* const* d_in, const int* in_sizes, int n_in,
                              void* d_out, int out_size)
{
    const float* x     = (const float*)d_in[0];
    const float* Win   = (const float*)d_in[1];
    const float* bin_  = (const float*)d_in[2];
    const float* wconv = (const float*)d_in[3];
    const float* Wout  = (const float*)d_in[4];
    const float* bout  = (const float*)d_in[5];
    float* out = (float*)d_out;

    __half *BCh, *yh, *xh, *Wih, *Woh;
    cudaGetSymbolAddress((void**)&BCh, g_BCh);
    cudaGetSymbolAddress((void**)&yh,  g_yh);
    cudaGetSymbolAddress((void**)&xh,  g_xh);
    cudaGetSymbolAddress((void**)&Wih, g_Wih);
    cudaGetSymbolAddress((void**)&Woh, g_Woh);

    cudaFuncSetAttribute(gemm_tc_f16<__half>, cudaFuncAttributeMaxDynamicSharedMemorySize, SMEM_DYN);
    cudaFuncSetAttribute(gemm_tc_f16<float>,  cudaFuncAttributeMaxDynamicSharedMemorySize, SMEM_DYN);

    const int M = MTOT;

    // convert inputs/weights to half
    {
        int n4 = M * DIM / 4;
        cvt_f16_kernel<<<(n4 + 255) / 256, 256>>>(x, xh, n4);
        n4 = 3 * DIM * DIM / 4;
        cvt_f16_kernel<<<(n4 + 255) / 256, 256>>>(Win, Wih, n4);
        n4 = DIM * DIM / 4;
        cvt_f16_kernel<<<(n4 + 255) / 256, 256>>>(Wout, Woh, n4);
    }

    // GEMM 1: BCh = half(xh @ Wih^T + bin)   (M x 3072, K=1024)
    {
        dim3 grid((3 * DIM) / BN, M / BM);
        gemm_tc_f16<__half><<<grid, 256, SMEM_DYN>>>(xh, Wih, bin_, BCh, M, 3 * DIM, DIM);
    }

    // gate + causal conv -> yh (half)
    {
        dim3 grid(DIM / 256, BATCH, SEQL / LCHUNK);
        gate_conv_kernel<<<grid, 256>>>(BCh, wconv, yh);
    }

    // GEMM 2: out = yh @ Woh^T + bout  (M x 1024, K=1024)
    {
        dim3 grid(DIM / BN, M / BM);
        gemm_tc_f16<float><<<grid, 256, SMEM_DYN>>>(yh, Woh, bout, out, M, DIM, DIM);
    }
}

// round 14
// speedup vs baseline: 1.1184x; 1.0097x over previous
#include <cuda_runtime.h>
#include <cuda_fp16.h>
#include <cstdint>
#include <cstddef>

// Problem constants
#define DIM   1024
#define BATCH 16
#define SEQL  2048
#define KCONV 3
#define MTOT  (BATCH * SEQL)   // 32768

// ---------------- scratch (static; no allocs allowed) ----------------
__device__ __align__(16) __half g_BCh[(size_t)MTOT * 3 * DIM]; // in_proj out (half)
__device__ __align__(16) __half g_yh [(size_t)MTOT * DIM];     // gated conv out (half)
__device__ __align__(16) __half g_xh [(size_t)MTOT * DIM];     // x in half
__device__ __align__(16) __half g_Wih[(size_t)3 * DIM * DIM];  // Win in half
__device__ __align__(16) __half g_Woh[(size_t)DIM * DIM];      // Wout in half

// ---------------- PTX helpers (plain sm_103 legal) ----------------
__device__ __forceinline__ void cp_async16(uint32_t dst, const void* src) {
    asm volatile("cp.async.cg.shared.global [%0], [%1], 16;" :: "r"(dst), "l"(src));
}
// one COMPLETING arrive on mbar when this thread's prior cp.asyncs finish.
// .noinc is essential: without it the pending count is incremented first (net zero).
__device__ __forceinline__ void cp_async_mbar_arrive(uint32_t mbar) {
    asm volatile("cp.async.mbarrier.arrive.noinc.shared.b64 [%0];" :: "r"(mbar) : "memory");
}
__device__ __forceinline__ void mbar_init(uint32_t mbar, uint32_t cnt) {
    asm volatile("mbarrier.init.shared.b64 [%0], %1;" :: "r"(mbar), "r"(cnt) : "memory");
}
__device__ __forceinline__ void mbar_arrive(uint32_t mbar) {
    asm volatile("mbarrier.arrive.shared.b64 _, [%0];" :: "r"(mbar) : "memory");
}
__device__ __forceinline__ void mbar_wait(uint32_t mbar, uint32_t parity) {
    uint32_t done;
    asm volatile(
        "{\n\t.reg .pred p;\n\t"
        "mbarrier.try_wait.parity.acquire.cta.shared::cta.b64 p, [%1], %2;\n\t"
        "selp.b32 %0, 1, 0, p;\n\t}"
        : "=r"(done) : "r"(mbar), "r"(parity) : "memory");
    if (!done) {
        asm volatile(
            "{\n\t.reg .pred P1;\n\t"
            "WL_%=:\n\t"
            "mbarrier.try_wait.parity.acquire.cta.shared::cta.b64 P1, [%0], %1, 0x989680;\n\t"
            "@P1 bra.uni WD_%=;\n\t"
            "bra.uni WL_%=;\n\t"
            "WD_%=:\n\t}"
            :: "r"(mbar), "r"(parity) : "memory");
    }
}
__device__ __forceinline__ uint32_t smem_u32(const void* p) {
    uint32_t a;
    asm("{ .reg .u64 t; cvta.to.shared.u64 t, %1; cvt.u32.u64 %0, t; }" : "=r"(a) : "l"(p));
    return a;
}
__device__ __forceinline__ void ldsm_x4(uint32_t* r, uint32_t addr) {
    asm volatile("ldmatrix.sync.aligned.m8n8.x4.shared.b16 {%0,%1,%2,%3}, [%4];"
        : "=r"(r[0]), "=r"(r[1]), "=r"(r[2]), "=r"(r[3]) : "r"(addr));
}
__device__ __forceinline__ void mma_f16(float* c, const uint32_t* a, const uint32_t* b)
{
    asm volatile(
        "mma.sync.aligned.m16n8k16.row.col.f32.f16.f16.f32 "
        "{%0,%1,%2,%3}, {%4,%5,%6,%7}, {%8,%9}, {%0,%1,%2,%3};"
        : "+f"(c[0]), "+f"(c[1]), "+f"(c[2]), "+f"(c[3])
        : "r"(a[0]), "r"(a[1]), "r"(a[2]), "r"(a[3]), "r"(b[0]), "r"(b[1]));
}

#define SW128(off) ((off) ^ (((off) >> 3) & 0x70))

// ---------------- GEMM tiling (128x128x64, 3 stages, 2 CTAs/SM) ----------------
#define BM 128
#define BN 128
#define BK 64                                   // 64 halfs = 128B rows
#define NSTAGE 3
#define A_BYTES (BM * 128)
#define STAGE_BYTES (BM * 128 + BN * 128)       // 32KB
#define SMEM_DYN (1024 + NSTAGE * STAGE_BYTES)  // 99328 -> 2 CTAs/SM

// fill one operand tile: nrows rows x 64 halfs (128B rows, SW128-swizzled)
__device__ __forceinline__ void fill_tile(uint32_t sbase, const __half* g, int nrows,
                                          int K, int k0, int tid)
{
    const int nch = nrows * 8;
    for (int idx = tid; idx < nch; idx += 256) {
        int row = idx >> 3;
        int c4  = idx & 7;
        const __half* src = g + (size_t)row * K + k0 + c4 * 8;
        uint32_t off = (uint32_t)(row * 128 + c4 * 16);
        cp_async16(sbase + SW128(off), src);
    }
}

// ---------------- fp16 tensor-core GEMM: C[m,n] = sum_k A[m,k]*B[n,k] + bias[n] ----------
// mbarrier full/empty pipeline; warp grid 2x4, warp tile 64x32.
template <typename OutT>
__global__ __launch_bounds__(256, 2)
void gemm_tc_f16(const __half* __restrict__ A,
                 const __half* __restrict__ B,
                 const float* __restrict__ bias,
                 OutT* __restrict__ C,
                 int M, int N, int K)
{
    extern __shared__ char smem[];
    const uint32_t sbase = smem_u32(smem);
    const int tid = threadIdx.x;
    const int bm = blockIdx.y * BM;
    const int bn = blockIdx.x * BN;

    // control region: full[s] at +0,8,16 ; empty[s] at +24,32,40
    const uint32_t mb_full  = sbase;
    const uint32_t mb_empty = sbase + 24;

    const uint32_t tile0 = (sbase + 1023) & ~1023u;

    const __half* Ag = A + (size_t)bm * K;
    const __half* Bg = B + (size_t)bn * K;
    const int NT = K / BK;   // 16

    const int w = tid >> 5, lane = tid & 31;
    const int wm = (w >> 2) * 64;   // warp M offset (0 or 64)
    const int wn = (w & 3) * 32;    // warp N offset (0..96)

    // --- ldmatrix per-lane addressing (SW128 folded) ---
    const uint32_t a_row  = (uint32_t)(lane & 15);
    const uint32_t a_xor  = (uint32_t)((lane & 7) << 4);
    const uint32_t a_ch   = (uint32_t)((lane >> 4) * 16);
    const uint32_t b_row  = (uint32_t)((lane & 7) + ((lane >> 4) & 1) * 8);
    const uint32_t b_xor  = (uint32_t)((lane & 7) << 4);
    const uint32_t b_ch   = (uint32_t)(((lane >> 3) & 1) * 16);

    const uint32_t aBase = tile0 + (uint32_t)wm * 128 + a_row * 128;
    const uint32_t bBase = tile0 + (uint32_t)A_BYTES + (uint32_t)wn * 128 + b_row * 128;

    if (tid == 0) {
#pragma unroll
        for (int s = 0; s < NSTAGE; s++) {
            mbar_init(mb_full  + s * 8, 256);
            mbar_init(mb_empty + s * 8, 256);
        }
    }
    __syncthreads();

    float acc[4][4][4];
#pragma unroll
    for (int a = 0; a < 4; a++)
#pragma unroll
        for (int b = 0; b < 4; b++)
#pragma unroll
            for (int c = 0; c < 4; c++) acc[a][b][c] = 0.0f;

    // prologue: fill all 3 stages (tiles 0..2); one cp-gated arrive per stage
#pragma unroll
    for (int p = 0; p < NSTAGE; p++) {
        uint32_t sA = tile0 + p * STAGE_BYTES;
        fill_tile(sA, Ag, BM, K, p * BK, tid);
        fill_tile(sA + A_BYTES, Bg, BN, K, p * BK, tid);
        cp_async_mbar_arrive(mb_full + p * 8);
    }

    int s = 0, ph = 0;
    for (int i = 0; i < NT; i++) {
        const uint32_t soff = (uint32_t)s * STAGE_BYTES;

        // consumer: wait for tile i's data
        mbar_wait(mb_full + s * 8, (uint32_t)ph);

        const uint32_t aS = aBase + soff;
        const uint32_t bS = bBase + soff;

        // compute tile i: 4 k16-steps; signal stage-empty right after the LAST LDSM
#pragma unroll
        for (int ks = 0; ks < 4; ks++) {
            const uint32_t kb = (uint32_t)(ks * 32);
            const uint32_t ca = (kb + a_ch) ^ a_xor;
            const uint32_t cb = (kb + b_ch) ^ b_xor;
            uint32_t afr[4][4], bfr[8];
#pragma unroll
            for (int mt = 0; mt < 4; mt++) ldsm_x4(afr[mt], aS + mt * 2048 + ca);
            ldsm_x4(&bfr[0], bS + cb);
            ldsm_x4(&bfr[4], bS + 2048 + cb);
            if (ks == 3) mbar_arrive(mb_empty + s * 8);   // done reading stage s
#pragma unroll
            for (int mt = 0; mt < 4; mt++)
#pragma unroll
                for (int nt = 0; nt < 4; nt++)
                    mma_f16(acc[mt][nt], afr[mt], &bfr[nt * 2]);
        }

        // producer: refill stage s with tile i+3 once everyone is done reading it
        if (i + NSTAGE < NT) {
            mbar_wait(mb_empty + s * 8, (uint32_t)ph);
            uint32_t sA = tile0 + soff;
            fill_tile(sA, Ag, BM, K, (i + NSTAGE) * BK, tid);
            fill_tile(sA + A_BYTES, Bg, BN, K, (i + NSTAGE) * BK, tid);
            cp_async_mbar_arrive(mb_full + s * 8);
        }

        s++; if (s >= NSTAGE) { s = 0; ph ^= 1; }
    }

    // epilogue: bias + store (fp32 or half per OutT)
#pragma unroll
    for (int mt = 0; mt < 4; mt++) {
#pragma unroll
        for (int nt = 0; nt < 4; nt++) {
            int row0 = bm + wm + mt * 16 + (lane >> 2);
            int col0 = bn + wn + nt * 8 + (lane & 3) * 2;
            float b0 = __ldg(bias + col0), b1 = __ldg(bias + col0 + 1);
            float v00 = acc[mt][nt][0] + b0, v01 = acc[mt][nt][1] + b1;
            float v10 = acc[mt][nt][2] + b0, v11 = acc[mt][nt][3] + b1;
            if (sizeof(OutT) == 4) {
                float* Cf = (float*)C;
                *(float2*)(Cf + (size_t)row0 * N + col0) = make_float2(v00, v01);
                *(float2*)(Cf + (size_t)(row0 + 8) * N + col0) = make_float2(v10, v11);
            } else {
                __half* Ch = (__half*)C;
                *(__half2*)(Ch + (size_t)row0 * N + col0) = __floats2half2_rn(v00, v01);
                *(__half2*)(Ch + (size_t)(row0 + 8) * N + col0) = __floats2half2_rn(v10, v11);
            }
        }
    }
}

// ---------------- elementwise fp32 -> half ----------------
__global__ __launch_bounds__(256)
void cvt_f16_kernel(const float* __restrict__ in, __half* __restrict__ out, int n4)
{
    int i = blockIdx.x * blockDim.x + threadIdx.x;
    if (i < n4) {
        float4 v = reinterpret_cast<const float4*>(in)[i];
        __half2 h01 = __floats2half2_rn(v.x, v.y);
        __half2 h23 = __floats2half2_rn(v.z, v.w);
        __half2 pk[2] = { h01, h23 };
        reinterpret_cast<uint2*>(out)[i] = *reinterpret_cast<const uint2*>(pk);
    }
}

// ---------------- gate + causal depthwise conv (K=3), half2 vectorized ----------------
// Each thread owns a channel PAIR (half2). Warp loads = full 128B lines.
#define LCHUNK 128
#define D2 (DIM / 2)          // 512 half2 channels
#define ROW2 (3 * DIM / 2)    // BCh row length in half2 units (1536)

__global__ __launch_bounds__(256)
void gate_conv_kernel(const __half2* __restrict__ BCx,
                      const float* __restrict__ wconv,
                      __half2* __restrict__ y)
{
    const int d2 = blockIdx.x * blockDim.x + threadIdx.x;   // 0..511
    const int b  = blockIdx.y;
    const int l0 = blockIdx.z * LCHUNK;

    const int c0 = 2 * d2, c1 = 2 * d2 + 1;
    const float2 w0 = make_float2(wconv[c0 * KCONV + 0], wconv[c1 * KCONV + 0]);
    const float2 w1 = make_float2(wconv[c0 * KCONV + 1], wconv[c1 * KCONV + 1]);
    const float2 w2 = make_float2(wconv[c0 * KCONV + 2], wconv[c1 * KCONV + 2]);

    const __half2* base = BCx + (size_t)b * SEQL * ROW2;

    float2 bxm2 = make_float2(0.f, 0.f), bxm1 = make_float2(0.f, 0.f);
    if (l0 >= 2) {
        const __half2* r = base + (size_t)(l0 - 2) * ROW2;
        float2 bg = __half22float2(r[d2]);
        float2 xg = __half22float2(r[2 * D2 + d2]);
        bxm2 = make_float2(bg.x * xg.x, bg.y * xg.y);
    }
    if (l0 >= 1) {
        const __half2* r = base + (size_t)(l0 - 1) * ROW2;
        float2 bg = __half22float2(r[d2]);
        float2 xg = __half22float2(r[2 * D2 + d2]);
        bxm1 = make_float2(bg.x * xg.x, bg.y * xg.y);
    }

#pragma unroll 4
    for (int l = l0; l < l0 + LCHUNK; l++) {
        const __half2* r = base + (size_t)l * ROW2;
        float2 bg = __half22float2(r[d2]);
        float2 cg = __half22float2(r[D2 + d2]);
        float2 xg = __half22float2(r[2 * D2 + d2]);
        float2 bx = make_float2(bg.x * xg.x, bg.y * xg.y);
        float cx = fmaf(w0.x, bxm2.x, fmaf(w1.x, bxm1.x, w2.x * bx.x));
        float cy = fmaf(w0.y, bxm2.y, fmaf(w1.y, bxm1.y, w2.y * bx.y));
        y[((size_t)b * SEQL + l) * D2 + d2] = __floats2half2_rn(cg.x * cx, cg.y * cy);
        bxm2 = bxm1;
        bxm1 = bx;
    }
}

// ---------------------------------------------------------------------------
extern "C" void kernel_launch(void* const* d_in, const int* in_sizes, int n_in,
                              void* d_out, int out_size)
{
    const float* x     = (const float*)d_in[0];
    const float* Win   = (const float*)d_in[1];
    const float* bin_  = (const float*)d_in[2];
    const float* wconv = (const float*)d_in[3];
    const float* Wout  = (const float*)d_in[4];
    const float* bout  = (const float*)d_in[5];
    float* out = (float*)d_out;

    __half *BCh, *yh, *xh, *Wih, *Woh;
    cudaGetSymbolAddress((void**)&BCh, g_BCh);
    cudaGetSymbolAddress((void**)&yh,  g_yh);
    cudaGetSymbolAddress((void**)&xh,  g_xh);
    cudaGetSymbolAddress((void**)&Wih, g_Wih);
    cudaGetSymbolAddress((void**)&Woh, g_Woh);

    cudaFuncSetAttribute(gemm_tc_f16<__half>, cudaFuncAttributeMaxDynamicSharedMemorySize, SMEM_DYN);
    cudaFuncSetAttribute(gemm_tc_f16<float>,  cudaFuncAttributeMaxDynamicSharedMemorySize, SMEM_DYN);

    const int M = MTOT;

    // convert inputs/weights to half
    {
        int n4 = M * DIM / 4;
        cvt_f16_kernel<<<(n4 + 255) / 256, 256>>>(x, xh, n4);
        n4 = 3 * DIM * DIM / 4;
        cvt_f16_kernel<<<(n4 + 255) / 256, 256>>>(Win, Wih, n4);
        n4 = DIM * DIM / 4;
        cvt_f16_kernel<<<(n4 + 255) / 256, 256>>>(Wout, Woh, n4);
    }

    // GEMM 1: BCh = half(xh @ Wih^T + bin)   (M x 3072, K=1024)
    {
        dim3 grid((3 * DIM) / BN, M / BM);
        gemm_tc_f16<__half><<<grid, 256, SMEM_DYN>>>(xh, Wih, bin_, BCh, M, 3 * DIM, DIM);
    }

    // gate + causal conv -> yh (half2 vectorized)
    {
        dim3 grid(D2 / 256, BATCH, SEQL / LCHUNK);
        gate_conv_kernel<<<grid, 256>>>((const __half2*)BCh, wconv, (__half2*)yh);
    }

    // GEMM 2: out = yh @ Woh^T + bout  (M x 1024, K=1024)
    {
        dim3 grid(DIM / BN, M / BM);
        gemm_tc_f16<float><<<grid, 256, SMEM_DYN>>>(yh, Woh, bout, out, M, DIM, DIM);
    }
}

// round 15
// speedup vs baseline: 1.1440x; 1.0230x over previous
#include <cuda_runtime.h>
#include <cuda_fp16.h>
#include <cstdint>
#include <cstddef>

// Problem constants
#define DIM   1024
#define BATCH 16
#define SEQL  2048
#define KCONV 3
#define MTOT  (BATCH * SEQL)   // 32768

// ---------------- scratch (static; no allocs allowed) ----------------
__device__ __align__(16) __half g_BCh[(size_t)MTOT * 3 * DIM]; // in_proj out (half)
__device__ __align__(16) __half g_yh [(size_t)MTOT * DIM];     // gated conv out (half)
__device__ __align__(16) __half g_xh [(size_t)MTOT * DIM];     // x in half
__device__ __align__(16) __half g_Wih[(size_t)3 * DIM * DIM];  // Win in half
__device__ __align__(16) __half g_Woh[(size_t)DIM * DIM];      // Wout in half

// ---------------- PTX helpers (plain sm_103 legal) ----------------
__device__ __forceinline__ void cp_async16(uint32_t dst, const void* src) {
    asm volatile("cp.async.cg.shared.global [%0], [%1], 16;" :: "r"(dst), "l"(src));
}
// one COMPLETING arrive on mbar when this thread's prior cp.asyncs finish.
// .noinc is essential: without it the pending count is incremented first (net zero).
__device__ __forceinline__ void cp_async_mbar_arrive(uint32_t mbar) {
    asm volatile("cp.async.mbarrier.arrive.noinc.shared.b64 [%0];" :: "r"(mbar) : "memory");
}
__device__ __forceinline__ void mbar_init(uint32_t mbar, uint32_t cnt) {
    asm volatile("mbarrier.init.shared.b64 [%0], %1;" :: "r"(mbar), "r"(cnt) : "memory");
}
__device__ __forceinline__ void mbar_arrive(uint32_t mbar) {
    asm volatile("mbarrier.arrive.shared.b64 _, [%0];" :: "r"(mbar) : "memory");
}
__device__ __forceinline__ void mbar_wait(uint32_t mbar, uint32_t parity) {
    uint32_t done;
    asm volatile(
        "{\n\t.reg .pred p;\n\t"
        "mbarrier.try_wait.parity.acquire.cta.shared::cta.b64 p, [%1], %2;\n\t"
        "selp.b32 %0, 1, 0, p;\n\t}"
        : "=r"(done) : "r"(mbar), "r"(parity) : "memory");
    if (!done) {
        asm volatile(
            "{\n\t.reg .pred P1;\n\t"
            "WL_%=:\n\t"
            "mbarrier.try_wait.parity.acquire.cta.shared::cta.b64 P1, [%0], %1, 0x989680;\n\t"
            "@P1 bra.uni WD_%=;\n\t"
            "bra.uni WL_%=;\n\t"
            "WD_%=:\n\t}"
            :: "r"(mbar), "r"(parity) : "memory");
    }
}
__device__ __forceinline__ uint32_t smem_u32(const void* p) {
    uint32_t a;
    asm("{ .reg .u64 t; cvta.to.shared.u64 t, %1; cvt.u32.u64 %0, t; }" : "=r"(a) : "l"(p));
    return a;
}
__device__ __forceinline__ void ldsm_x4(uint32_t* r, uint32_t addr) {
    asm volatile("ldmatrix.sync.aligned.m8n8.x4.shared.b16 {%0,%1,%2,%3}, [%4];"
        : "=r"(r[0]), "=r"(r[1]), "=r"(r[2]), "=r"(r[3]) : "r"(addr));
}
__device__ __forceinline__ void mma_f16(float* c, const uint32_t* a, const uint32_t* b)
{
    asm volatile(
        "mma.sync.aligned.m16n8k16.row.col.f32.f16.f16.f32 "
        "{%0,%1,%2,%3}, {%4,%5,%6,%7}, {%8,%9}, {%0,%1,%2,%3};"
        : "+f"(c[0]), "+f"(c[1]), "+f"(c[2]), "+f"(c[3])
        : "r"(a[0]), "r"(a[1]), "r"(a[2]), "r"(a[3]), "r"(b[0]), "r"(b[1]));
}

#define SW128(off) ((off) ^ (((off) >> 3) & 0x70))

// ---------------- GEMM tiling (128x128x64, 3 stages, 2 CTAs/SM) ----------------
#define BM 128
#define BN 128
#define BK 64                                   // 64 halfs = 128B rows
#define NSTAGE 3
#define A_BYTES (BM * 128)
#define STAGE_BYTES (BM * 128 + BN * 128)       // 32KB
#define SMEM_DYN (1024 + NSTAGE * STAGE_BYTES)  // 99328 -> 2 CTAs/SM

// fill one operand tile: nrows rows x 64 halfs (128B rows, SW128-swizzled)
__device__ __forceinline__ void fill_tile(uint32_t sbase, const __half* g, int nrows,
                                          int K, int k0, int tid)
{
    const int nch = nrows * 8;
    for (int idx = tid; idx < nch; idx += 256) {
        int row = idx >> 3;
        int c4  = idx & 7;
        const __half* src = g + (size_t)row * K + k0 + c4 * 8;
        uint32_t off = (uint32_t)(row * 128 + c4 * 16);
        cp_async16(sbase + SW128(off), src);
    }
}

// ---------------- fp16 tensor-core GEMM: C[m,n] = sum_k A[m,k]*B[n,k] + bias[n] ----------
// mbarrier full/empty pipeline; warp grid 2x4, warp tile 64x32.  (FROZEN from R13/R14.)
template <typename OutT>
__global__ __launch_bounds__(256, 2)
void gemm_tc_f16(const __half* __restrict__ A,
                 const __half* __restrict__ B,
                 const float* __restrict__ bias,
                 OutT* __restrict__ C,
                 int M, int N, int K)
{
    extern __shared__ char smem[];
    const uint32_t sbase = smem_u32(smem);
    const int tid = threadIdx.x;
    const int bm = blockIdx.y * BM;
    const int bn = blockIdx.x * BN;

    // control region: full[s] at +0,8,16 ; empty[s] at +24,32,40
    const uint32_t mb_full  = sbase;
    const uint32_t mb_empty = sbase + 24;

    const uint32_t tile0 = (sbase + 1023) & ~1023u;

    const __half* Ag = A + (size_t)bm * K;
    const __half* Bg = B + (size_t)bn * K;
    const int NT = K / BK;   // 16

    const int w = tid >> 5, lane = tid & 31;
    const int wm = (w >> 2) * 64;   // warp M offset (0 or 64)
    const int wn = (w & 3) * 32;    // warp N offset (0..96)

    // --- ldmatrix per-lane addressing (SW128 folded) ---
    const uint32_t a_row  = (uint32_t)(lane & 15);
    const uint32_t a_xor  = (uint32_t)((lane & 7) << 4);
    const uint32_t a_ch   = (uint32_t)((lane >> 4) * 16);
    const uint32_t b_row  = (uint32_t)((lane & 7) + ((lane >> 4) & 1) * 8);
    const uint32_t b_xor  = (uint32_t)((lane & 7) << 4);
    const uint32_t b_ch   = (uint32_t)(((lane >> 3) & 1) * 16);

    const uint32_t aBase = tile0 + (uint32_t)wm * 128 + a_row * 128;
    const uint32_t bBase = tile0 + (uint32_t)A_BYTES + (uint32_t)wn * 128 + b_row * 128;

    if (tid == 0) {
#pragma unroll
        for (int s = 0; s < NSTAGE; s++) {
            mbar_init(mb_full  + s * 8, 256);
            mbar_init(mb_empty + s * 8, 256);
        }
    }
    __syncthreads();

    float acc[4][4][4];
#pragma unroll
    for (int a = 0; a < 4; a++)
#pragma unroll
        for (int b = 0; b < 4; b++)
#pragma unroll
            for (int c = 0; c < 4; c++) acc[a][b][c] = 0.0f;

    // prologue: fill all 3 stages (tiles 0..2); one cp-gated arrive per stage
#pragma unroll
    for (int p = 0; p < NSTAGE; p++) {
        uint32_t sA = tile0 + p * STAGE_BYTES;
        fill_tile(sA, Ag, BM, K, p * BK, tid);
        fill_tile(sA + A_BYTES, Bg, BN, K, p * BK, tid);
        cp_async_mbar_arrive(mb_full + p * 8);
    }

    int s = 0, ph = 0;
    for (int i = 0; i < NT; i++) {
        const uint32_t soff = (uint32_t)s * STAGE_BYTES;

        // consumer: wait for tile i's data
        mbar_wait(mb_full + s * 8, (uint32_t)ph);

        const uint32_t aS = aBase + soff;
        const uint32_t bS = bBase + soff;

        // compute tile i: 4 k16-steps; signal stage-empty right after the LAST LDSM
#pragma unroll
        for (int ks = 0; ks < 4; ks++) {
            const uint32_t kb = (uint32_t)(ks * 32);
            const uint32_t ca = (kb + a_ch) ^ a_xor;
            const uint32_t cb = (kb + b_ch) ^ b_xor;
            uint32_t afr[4][4], bfr[8];
#pragma unroll
            for (int mt = 0; mt < 4; mt++) ldsm_x4(afr[mt], aS + mt * 2048 + ca);
            ldsm_x4(&bfr[0], bS + cb);
            ldsm_x4(&bfr[4], bS + 2048 + cb);
            if (ks == 3) mbar_arrive(mb_empty + s * 8);   // done reading stage s
#pragma unroll
            for (int mt = 0; mt < 4; mt++)
#pragma unroll
                for (int nt = 0; nt < 4; nt++)
                    mma_f16(acc[mt][nt], afr[mt], &bfr[nt * 2]);
        }

        // producer: refill stage s with tile i+3 once everyone is done reading it
        if (i + NSTAGE < NT) {
            mbar_wait(mb_empty + s * 8, (uint32_t)ph);
            uint32_t sA = tile0 + soff;
            fill_tile(sA, Ag, BM, K, (i + NSTAGE) * BK, tid);
            fill_tile(sA + A_BYTES, Bg, BN, K, (i + NSTAGE) * BK, tid);
            cp_async_mbar_arrive(mb_full + s * 8);
        }

        s++; if (s >= NSTAGE) { s = 0; ph ^= 1; }
    }

    // epilogue: bias + store (fp32 or half per OutT)
#pragma unroll
    for (int mt = 0; mt < 4; mt++) {
#pragma unroll
        for (int nt = 0; nt < 4; nt++) {
            int row0 = bm + wm + mt * 16 + (lane >> 2);
            int col0 = bn + wn + nt * 8 + (lane & 3) * 2;
            float b0 = __ldg(bias + col0), b1 = __ldg(bias + col0 + 1);
            float v00 = acc[mt][nt][0] + b0, v01 = acc[mt][nt][1] + b1;
            float v10 = acc[mt][nt][2] + b0, v11 = acc[mt][nt][3] + b1;
            if (sizeof(OutT) == 4) {
                float* Cf = (float*)C;
                *(float2*)(Cf + (size_t)row0 * N + col0) = make_float2(v00, v01);
                *(float2*)(Cf + (size_t)(row0 + 8) * N + col0) = make_float2(v10, v11);
            } else {
                __half* Ch = (__half*)C;
                *(__half2*)(Ch + (size_t)row0 * N + col0) = __floats2half2_rn(v00, v01);
                *(__half2*)(Ch + (size_t)(row0 + 8) * N + col0) = __floats2half2_rn(v10, v11);
            }
        }
    }
}

// ---------------- merged elementwise fp32 -> half (x ‖ Win ‖ Wout in one launch) -------
#define N4_X  (MTOT * DIM / 4)            // 8388608
#define N4_WI (3 * DIM * DIM / 4)         // 786432
#define N4_WO (DIM * DIM / 4)             // 262144
#define N4_TOT (N4_X + N4_WI + N4_WO)

__global__ __launch_bounds__(256)
void cvt_f16_all(const float* __restrict__ x,  __half* __restrict__ xh,
                 const float* __restrict__ wi, __half* __restrict__ wih,
                 const float* __restrict__ wo, __half* __restrict__ woh)
{
    int i = blockIdx.x * blockDim.x + threadIdx.x;
    if (i >= N4_TOT) return;
    const float* in;
    __half* out;
    int j;
    if (i < N4_X)              { in = x;  out = xh;  j = i; }
    else if (i < N4_X + N4_WI) { in = wi; out = wih; j = i - N4_X; }
    else                       { in = wo; out = woh; j = i - N4_X - N4_WI; }
    float4 v = reinterpret_cast<const float4*>(in)[j];
    __half2 pk[2] = { __floats2half2_rn(v.x, v.y), __floats2half2_rn(v.z, v.w) };
    reinterpret_cast<uint2*>(out)[j] = *reinterpret_cast<const uint2*>(pk);
}

// ---------------- gate + causal depthwise conv (K=3), half2, short chunks ----------------
// Each thread owns a channel PAIR (half2); LCHUNK=32 for 4x more CTA parallelism.
#define LCHUNK 32
#define D2 (DIM / 2)          // 512 half2 channels
#define ROW2 (3 * DIM / 2)    // BCh row length in half2 units (1536)

__global__ __launch_bounds__(256)
void gate_conv_kernel(const __half2* __restrict__ BCx,
                      const float* __restrict__ wconv,
                      __half2* __restrict__ y)
{
    const int d2 = blockIdx.x * blockDim.x + threadIdx.x;   // 0..511
    const int b  = blockIdx.y;
    const int l0 = blockIdx.z * LCHUNK;

    const int c0 = 2 * d2, c1 = 2 * d2 + 1;
    const float2 w0 = make_float2(wconv[c0 * KCONV + 0], wconv[c1 * KCONV + 0]);
    const float2 w1 = make_float2(wconv[c0 * KCONV + 1], wconv[c1 * KCONV + 1]);
    const float2 w2 = make_float2(wconv[c0 * KCONV + 2], wconv[c1 * KCONV + 2]);

    const __half2* base = BCx + (size_t)b * SEQL * ROW2;

    float2 bxm2 = make_float2(0.f, 0.f), bxm1 = make_float2(0.f, 0.f);
    if (l0 >= 2) {
        const __half2* r = base + (size_t)(l0 - 2) * ROW2;
        float2 bg = __half22float2(r[d2]);
        float2 xg = __half22float2(r[2 * D2 + d2]);
        bxm2 = make_float2(bg.x * xg.x, bg.y * xg.y);
    }
    if (l0 >= 1) {
        const __half2* r = base + (size_t)(l0 - 1) * ROW2;
        float2 bg = __half22float2(r[d2]);
        float2 xg = __half22float2(r[2 * D2 + d2]);
        bxm1 = make_float2(bg.x * xg.x, bg.y * xg.y);
    }

#pragma unroll 4
    for (int l = l0; l < l0 + LCHUNK; l++) {
        const __half2* r = base + (size_t)l * ROW2;
        float2 bg = __half22float2(r[d2]);
        float2 cg = __half22float2(r[D2 + d2]);
        float2 xg = __half22float2(r[2 * D2 + d2]);
        float2 bx = make_float2(bg.x * xg.x, bg.y * xg.y);
        float cx = fmaf(w0.x, bxm2.x, fmaf(w1.x, bxm1.x, w2.x * bx.x));
        float cy = fmaf(w0.y, bxm2.y, fmaf(w1.y, bxm1.y, w2.y * bx.y));
        y[((size_t)b * SEQL + l) * D2 + d2] = __floats2half2_rn(cg.x * cx, cg.y * cy);
        bxm2 = bxm1;
        bxm1 = bx;
    }
}

// ---------------------------------------------------------------------------
extern "C" void kernel_launch(void* const* d_in, const int* in_sizes, int n_in,
                              void* d_out, int out_size)
{
    const float* x     = (const float*)d_in[0];
    const float* Win   = (const float*)d_in[1];
    const float* bin_  = (const float*)d_in[2];
    const float* wconv = (const float*)d_in[3];
    const float* Wout  = (const float*)d_in[4];
    const float* bout  = (const float*)d_in[5];
    float* out = (float*)d_out;

    __half *BCh, *yh, *xh, *Wih, *Woh;
    cudaGetSymbolAddress((void**)&BCh, g_BCh);
    cudaGetSymbolAddress((void**)&yh,  g_yh);
    cudaGetSymbolAddress((void**)&xh,  g_xh);
    cudaGetSymbolAddress((void**)&Wih, g_Wih);
    cudaGetSymbolAddress((void**)&Woh, g_Woh);

    cudaFuncSetAttribute(gemm_tc_f16<__half>, cudaFuncAttributeMaxDynamicSharedMemorySize, SMEM_DYN);
    cudaFuncSetAttribute(gemm_tc_f16<float>,  cudaFuncAttributeMaxDynamicSharedMemorySize, SMEM_DYN);

    const int M = MTOT;

    // convert inputs/weights to half (single merged launch)
    cvt_f16_all<<<(N4_TOT + 255) / 256, 256>>>(x, xh, Win, Wih, Wout, Woh);

    // GEMM 1: BCh = half(xh @ Wih^T + bin)   (M x 3072, K=1024)
    {
        dim3 grid((3 * DIM) / BN, M / BM);
        gemm_tc_f16<__half><<<grid, 256, SMEM_DYN>>>(xh, Wih, bin_, BCh, M, 3 * DIM, DIM);
    }

    // gate + causal conv -> yh (half2 vectorized, short chunks)
    {
        dim3 grid(D2 / 256, BATCH, SEQL / LCHUNK);
        gate_conv_kernel<<<grid, 256>>>((const __half2*)BCh, wconv, (__half2*)yh);
    }

    // GEMM 2: out = yh @ Woh^T + bout  (M x 1024, K=1024)
    {
        dim3 grid(DIM / BN, M / BM);
        gemm_tc_f16<float><<<grid, 256, SMEM_DYN>>>(yh, Woh, bout, out, M, DIM, DIM);
    }
}

// round 16
// speedup vs baseline: 1.3036x; 1.1394x over previous
#include <cuda_runtime.h>
#include <cuda_fp16.h>
#include <cstdint>
#include <cstddef>

// Problem constants
#define DIM   1024
#define BATCH 16
#define SEQL  2048
#define KCONV 3
#define MTOT  (BATCH * SEQL)   // 32768
#define GK    1024             // GEMM K (both GEMMs), compile-time

// ---------------- scratch (static; no allocs allowed) ----------------
__device__ __align__(16) __half g_BCh[(size_t)MTOT * 3 * DIM]; // in_proj out (half)
__device__ __align__(16) __half g_yh [(size_t)MTOT * DIM];     // gated conv out (half)
__device__ __align__(16) __half g_xh [(size_t)MTOT * DIM];     // x in half
__device__ __align__(16) __half g_Wih[(size_t)3 * DIM * DIM];  // Win in half
__device__ __align__(16) __half g_Woh[(size_t)DIM * DIM];      // Wout in half

// ---------------- PTX helpers (plain sm_103 legal) ----------------
__device__ __forceinline__ void cp_async16(uint32_t dst, const void* src) {
    asm volatile("cp.async.cg.shared.global [%0], [%1], 16;" :: "r"(dst), "l"(src));
}
// one COMPLETING arrive on mbar when this thread's prior cp.asyncs finish (.noinc!).
__device__ __forceinline__ void cp_async_mbar_arrive(uint32_t mbar) {
    asm volatile("cp.async.mbarrier.arrive.noinc.shared.b64 [%0];" :: "r"(mbar) : "memory");
}
__device__ __forceinline__ void mbar_init(uint32_t mbar, uint32_t cnt) {
    asm volatile("mbarrier.init.shared.b64 [%0], %1;" :: "r"(mbar), "r"(cnt) : "memory");
}
__device__ __forceinline__ void mbar_arrive(uint32_t mbar) {
    asm volatile("mbarrier.arrive.shared.b64 _, [%0];" :: "r"(mbar) : "memory");
}
__device__ __forceinline__ void mbar_wait(uint32_t mbar, uint32_t parity) {
    uint32_t done;
    asm volatile(
        "{\n\t.reg .pred p;\n\t"
        "mbarrier.try_wait.parity.acquire.cta.shared::cta.b64 p, [%1], %2;\n\t"
        "selp.b32 %0, 1, 0, p;\n\t}"
        : "=r"(done) : "r"(mbar), "r"(parity) : "memory");
    if (!done) {
        asm volatile(
            "{\n\t.reg .pred P1;\n\t"
            "WL_%=:\n\t"
            "mbarrier.try_wait.parity.acquire.cta.shared::cta.b64 P1, [%0], %1, 0x989680;\n\t"
            "@P1 bra.uni WD_%=;\n\t"
            "bra.uni WL_%=;\n\t"
            "WD_%=:\n\t}"
            :: "r"(mbar), "r"(parity) : "memory");
    }
}
__device__ __forceinline__ uint32_t smem_u32(const void* p) {
    uint32_t a;
    asm("{ .reg .u64 t; cvta.to.shared.u64 t, %1; cvt.u32.u64 %0, t; }" : "=r"(a) : "l"(p));
    return a;
}
__device__ __forceinline__ void ldsm_x4(uint32_t* r, uint32_t addr) {
    asm volatile("ldmatrix.sync.aligned.m8n8.x4.shared.b16 {%0,%1,%2,%3}, [%4];"
        : "=r"(r[0]), "=r"(r[1]), "=r"(r[2]), "=r"(r[3]) : "r"(addr));
}
__device__ __forceinline__ void mma_f16(float* c, const uint32_t* a, const uint32_t* b)
{
    asm volatile(
        "mma.sync.aligned.m16n8k16.row.col.f32.f16.f16.f32 "
        "{%0,%1,%2,%3}, {%4,%5,%6,%7}, {%8,%9}, {%0,%1,%2,%3};"
        : "+f"(c[0]), "+f"(c[1]), "+f"(c[2]), "+f"(c[3])
        : "r"(a[0]), "r"(a[1]), "r"(a[2]), "r"(a[3]), "r"(b[0]), "r"(b[1]));
}

#define SW128(off) ((off) ^ (((off) >> 3) & 0x70))

// ---------------- GEMM tiling (128x128x64, 3 stages, 2 CTAs/SM) ----------------
#define BM 128
#define BN 128
#define BK 64                                   // 64 halfs = 128B rows
#define NSTAGE 3
#define A_BYTES (BM * 128)
#define STAGE_BYTES (BM * 128 + BN * 128)       // 32KB
#define SMEM_DYN (1024 + NSTAGE * STAGE_BYTES)  // 99328 -> 2 CTAs/SM

// Strength-reduced stage fill: per-thread chunk-0 bases precomputed; chunk t is a
// compile-time offset (+t*4096 smem, +t*32*GK halfs global). Zero per-chunk ALU.
__device__ __forceinline__ void fill_stage(uint32_t stage_base,
                                           const __half* aSrcT, const __half* bSrcT,
                                           uint32_t dOff, int k0)
{
#pragma unroll
    for (int t = 0; t < 4; t++)
        cp_async16(stage_base + dOff + t * 4096u, aSrcT + k0 + t * 32 * GK);
#pragma unroll
    for (int t = 0; t < 4; t++)
        cp_async16(stage_base + A_BYTES + dOff + t * 4096u, bSrcT + k0 + t * 32 * GK);
}

// ---------------- fp16 tensor-core GEMM: C[m,n] = sum_k A[m,k]*B[n,k] + bias[n] ----------
// mbarrier full/empty pipeline; warp grid 2x4, warp tile 64x32. K == GK (1024).
template <typename OutT>
__global__ __launch_bounds__(256, 2)
void gemm_tc_f16(const __half* __restrict__ A,
                 const __half* __restrict__ B,
                 const float* __restrict__ bias,
                 OutT* __restrict__ C,
                 int M, int N)
{
    extern __shared__ char smem[];
    const uint32_t sbase = smem_u32(smem);
    const int tid = threadIdx.x;
    const int bm = blockIdx.y * BM;
    const int bn = blockIdx.x * BN;

    // control region: full[s] at +0,8,16 ; empty[s] at +24,32,40
    const uint32_t mb_full  = sbase;
    const uint32_t mb_empty = sbase + 24;

    const uint32_t tile0 = (sbase + 1023) & ~1023u;

    const int NT = GK / BK;   // 16

    // per-thread fill bases (chunk 0): row0 = tid>>3, c4 = tid&7
    const __half* aSrcT = A + (size_t)(bm + (tid >> 3)) * GK + (tid & 7) * 8;
    const __half* bSrcT = B + (size_t)(bn + (tid >> 3)) * GK + (tid & 7) * 8;
    const uint32_t dOff = SW128((uint32_t)((tid >> 3) * 128 + (tid & 7) * 16));

    const int w = tid >> 5, lane = tid & 31;
    const int wm = (w >> 2) * 64;   // warp M offset (0 or 64)
    const int wn = (w & 3) * 32;    // warp N offset (0..96)

    // --- ldmatrix per-lane addressing (SW128 folded) ---
    const uint32_t a_row  = (uint32_t)(lane & 15);
    const uint32_t a_xor  = (uint32_t)((lane & 7) << 4);
    const uint32_t a_ch   = (uint32_t)((lane >> 4) * 16);
    const uint32_t b_row  = (uint32_t)((lane & 7) + ((lane >> 4) & 1) * 8);
    const uint32_t b_xor  = (uint32_t)((lane & 7) << 4);
    const uint32_t b_ch   = (uint32_t)(((lane >> 3) & 1) * 16);

    const uint32_t aBase = tile0 + (uint32_t)wm * 128 + a_row * 128;
    const uint32_t bBase = tile0 + (uint32_t)A_BYTES + (uint32_t)wn * 128 + b_row * 128;

    if (tid == 0) {
#pragma unroll
        for (int s = 0; s < NSTAGE; s++) {
            mbar_init(mb_full  + s * 8, 256);
            mbar_init(mb_empty + s * 8, 256);
        }
    }
    __syncthreads();

    float acc[4][4][4];
#pragma unroll
    for (int a = 0; a < 4; a++)
#pragma unroll
        for (int b = 0; b < 4; b++)
#pragma unroll
            for (int c = 0; c < 4; c++) acc[a][b][c] = 0.0f;

    // prologue: fill all 3 stages (tiles 0..2); one cp-gated arrive per stage
#pragma unroll
    for (int p = 0; p < NSTAGE; p++) {
        fill_stage(tile0 + p * STAGE_BYTES, aSrcT, bSrcT, dOff, p * BK);
        cp_async_mbar_arrive(mb_full + p * 8);
    }

    int s = 0, ph = 0;
    for (int i = 0; i < NT; i++) {
        const uint32_t soff = (uint32_t)s * STAGE_BYTES;

        // consumer: wait for tile i's data
        mbar_wait(mb_full + s * 8, (uint32_t)ph);

        const uint32_t aS = aBase + soff;
        const uint32_t bS = bBase + soff;

        // compute tile i: 4 k16-steps; signal stage-empty right after the LAST LDSM
#pragma unroll
        for (int ks = 0; ks < 4; ks++) {
            const uint32_t kb = (uint32_t)(ks * 32);
            const uint32_t ca = (kb + a_ch) ^ a_xor;
            const uint32_t cb = (kb + b_ch) ^ b_xor;
            uint32_t afr[4][4], bfr[8];
#pragma unroll
            for (int mt = 0; mt < 4; mt++) ldsm_x4(afr[mt], aS + mt * 2048 + ca);
            ldsm_x4(&bfr[0], bS + cb);
            ldsm_x4(&bfr[4], bS + 2048 + cb);
            if (ks == 3) mbar_arrive(mb_empty + s * 8);   // done reading stage s
#pragma unroll
            for (int mt = 0; mt < 4; mt++)
#pragma unroll
                for (int nt = 0; nt < 4; nt++)
                    mma_f16(acc[mt][nt], afr[mt], &bfr[nt * 2]);
        }

        // producer: refill stage s with tile i+3 once everyone is done reading it
        if (i + NSTAGE < NT) {
            mbar_wait(mb_empty + s * 8, (uint32_t)ph);
            fill_stage(tile0 + soff, aSrcT, bSrcT, dOff, (i + NSTAGE) * BK);
            cp_async_mbar_arrive(mb_full + s * 8);
        }

        s++; if (s >= NSTAGE) { s = 0; ph ^= 1; }
    }

    // epilogue: bias + store (fp32 or half per OutT)
#pragma unroll
    for (int mt = 0; mt < 4; mt++) {
#pragma unroll
        for (int nt = 0; nt < 4; nt++) {
            int row0 = bm + wm + mt * 16 + (lane >> 2);
            int col0 = bn + wn + nt * 8 + (lane & 3) * 2;
            float b0 = __ldg(bias + col0), b1 = __ldg(bias + col0 + 1);
            float v00 = acc[mt][nt][0] + b0, v01 = acc[mt][nt][1] + b1;
            float v10 = acc[mt][nt][2] + b0, v11 = acc[mt][nt][3] + b1;
            if (sizeof(OutT) == 4) {
                float* Cf = (float*)C;
                *(float2*)(Cf + (size_t)row0 * N + col0) = make_float2(v00, v01);
                *(float2*)(Cf + (size_t)(row0 + 8) * N + col0) = make_float2(v10, v11);
            } else {
                __half* Ch = (__half*)C;
                *(__half2*)(Ch + (size_t)row0 * N + col0) = __floats2half2_rn(v00, v01);
                *(__half2*)(Ch + (size_t)(row0 + 8) * N + col0) = __floats2half2_rn(v10, v11);
            }
        }
    }
}

// ---------------- merged elementwise fp32 -> half (x ‖ Win ‖ Wout in one launch) -------
#define N4_X  (MTOT * DIM / 4)            // 8388608
#define N4_WI (3 * DIM * DIM / 4)         // 786432
#define N4_WO (DIM * DIM / 4)             // 262144
#define N4_TOT (N4_X + N4_WI + N4_WO)

__global__ __launch_bounds__(256)
void cvt_f16_all(const float* __restrict__ x,  __half* __restrict__ xh,
                 const float* __restrict__ wi, __half* __restrict__ wih,
                 const float* __restrict__ wo, __half* __restrict__ woh)
{
    int i = blockIdx.x * blockDim.x + threadIdx.x;
    if (i >= N4_TOT) return;
    const float* in;
    __half* out;
    int j;
    if (i < N4_X)              { in = x;  out = xh;  j = i; }
    else if (i < N4_X + N4_WI) { in = wi; out = wih; j = i - N4_X; }
    else                       { in = wo; out = woh; j = i - N4_X - N4_WI; }
    float4 v = reinterpret_cast<const float4*>(in)[j];
    __half2 pk[2] = { __floats2half2_rn(v.x, v.y), __floats2half2_rn(v.z, v.w) };
    reinterpret_cast<uint2*>(out)[j] = *reinterpret_cast<const uint2*>(pk);
}

// ---------------- gate + causal depthwise conv (K=3), half2, short chunks ----------------
#define LCHUNK 32
#define D2 (DIM / 2)          // 512 half2 channels
#define ROW2 (3 * DIM / 2)    // BCh row length in half2 units (1536)

__global__ __launch_bounds__(256)
void gate_conv_kernel(const __half2* __restrict__ BCx,
                      const float* __restrict__ wconv,
                      __half2* __restrict__ y)
{
    const int d2 = blockIdx.x * blockDim.x + threadIdx.x;   // 0..511
    const int b  = blockIdx.y;
    const int l0 = blockIdx.z * LCHUNK;

    const int c0 = 2 * d2, c1 = 2 * d2 + 1;
    const float2 w0 = make_float2(wconv[c0 * KCONV + 0], wconv[c1 * KCONV + 0]);
    const float2 w1 = make_float2(wconv[c0 * KCONV + 1], wconv[c1 * KCONV + 1]);
    const float2 w2 = make_float2(wconv[c0 * KCONV + 2], wconv[c1 * KCONV + 2]);

    const __half2* base = BCx + (size_t)b * SEQL * ROW2;

    float2 bxm2 = make_float2(0.f, 0.f), bxm1 = make_float2(0.f, 0.f);
    if (l0 >= 2) {
        const __half2* r = base + (size_t)(l0 - 2) * ROW2;
        float2 bg = __half22float2(r[d2]);
        float2 xg = __half22float2(r[2 * D2 + d2]);
        bxm2 = make_float2(bg.x * xg.x, bg.y * xg.y);
    }
    if (l0 >= 1) {
        const __half2* r = base + (size_t)(l0 - 1) * ROW2;
        float2 bg = __half22float2(r[d2]);
        float2 xg = __half22float2(r[2 * D2 + d2]);
        bxm1 = make_float2(bg.x * xg.x, bg.y * xg.y);
    }

#pragma unroll 4
    for (int l = l0; l < l0 + LCHUNK; l++) {
        const __half2* r = base + (size_t)l * ROW2;
        float2 bg = __half22float2(r[d2]);
        float2 cg = __half22float2(r[D2 + d2]);
        float2 xg = __half22float2(r[2 * D2 + d2]);
        float2 bx = make_float2(bg.x * xg.x, bg.y * xg.y);
        float cx = fmaf(w0.x, bxm2.x, fmaf(w1.x, bxm1.x, w2.x * bx.x));
        float cy = fmaf(w0.y, bxm2.y, fmaf(w1.y, bxm1.y, w2.y * bx.y));
        y[((size_t)b * SEQL + l) * D2 + d2] = __floats2half2_rn(cg.x * cx, cg.y * cy);
        bxm2 = bxm1;
        bxm1 = bx;
    }
}

// ---------------------------------------------------------------------------
extern "C" void kernel_launch(void* const* d_in, const int* in_sizes, int n_in,
                              void* d_out, int out_size)
{
    const float* x     = (const float*)d_in[0];
    const float* Win   = (const float*)d_in[1];
    const float* bin_  = (const float*)d_in[2];
    const float* wconv = (const float*)d_in[3];
    const float* Wout  = (const float*)d_in[4];
    const float* bout  = (const float*)d_in[5];
    float* out = (float*)d_out;

    __half *BCh, *yh, *xh, *Wih, *Woh;
    cudaGetSymbolAddress((void**)&BCh, g_BCh);
    cudaGetSymbolAddress((void**)&yh,  g_yh);
    cudaGetSymbolAddress((void**)&xh,  g_xh);
    cudaGetSymbolAddress((void**)&Wih, g_Wih);
    cudaGetSymbolAddress((void**)&Woh, g_Woh);

    cudaFuncSetAttribute(gemm_tc_f16<__half>, cudaFuncAttributeMaxDynamicSharedMemorySize, SMEM_DYN);
    cudaFuncSetAttribute(gemm_tc_f16<float>,  cudaFuncAttributeMaxDynamicSharedMemorySize, SMEM_DYN);

    const int M = MTOT;

    // convert inputs/weights to half (single merged launch)
    cvt_f16_all<<<(N4_TOT + 255) / 256, 256>>>(x, xh, Win, Wih, Wout, Woh);

    // GEMM 1: BCh = half(xh @ Wih^T + bin)   (M x 3072, K=1024)
    {
        dim3 grid((3 * DIM) / BN, M / BM);
        gemm_tc_f16<__half><<<grid, 256, SMEM_DYN>>>(xh, Wih, bin_, BCh, M, 3 * DIM);
    }

    // gate + causal conv -> yh (half2 vectorized, short chunks)
    {
        dim3 grid(D2 / 256, BATCH, SEQL / LCHUNK);
        gate_conv_kernel<<<grid, 256>>>((const __half2*)BCh, wconv, (__half2*)yh);
    }

    // GEMM 2: out = yh @ Woh^T + bout  (M x 1024, K=1024)
    {
        dim3 grid(DIM / BN, M / BM);
        gemm_tc_f16<float><<<grid, 256, SMEM_DYN>>>(yh, Woh, bout, out, M, DIM);
    }
}

// round 17
// speedup vs baseline: 1.3457x; 1.0323x over previous
#include <cuda_runtime.h>
#include <cuda_fp16.h>
#include <cstdint>
#include <cstddef>

// Problem constants
#define DIM   1024
#define BATCH 16
#define SEQL  2048
#define KCONV 3
#define MTOT  (BATCH * SEQL)   // 32768
#define GK    1024             // GEMM K (both GEMMs), compile-time

// ---------------- scratch (static; no allocs allowed) ----------------
__device__ __align__(16) __half g_BCh[(size_t)MTOT * 3 * DIM]; // in_proj out (half)
__device__ __align__(16) __half g_yh [(size_t)MTOT * DIM];     // gated conv out (half)
__device__ __align__(16) __half g_xh [(size_t)MTOT * DIM];     // x in half
__device__ __align__(16) __half g_Wih[(size_t)3 * DIM * DIM];  // Win in half
__device__ __align__(16) __half g_Woh[(size_t)DIM * DIM];      // Wout in half

// ---------------- PTX helpers (plain sm_103 legal) ----------------
__device__ __forceinline__ void cp_async16(uint32_t dst, const void* src) {
    asm volatile("cp.async.cg.shared.global [%0], [%1], 16;" :: "r"(dst), "l"(src));
}
// one COMPLETING arrive on mbar when this thread's prior cp.asyncs finish (.noinc!).
__device__ __forceinline__ void cp_async_mbar_arrive(uint32_t mbar) {
    asm volatile("cp.async.mbarrier.arrive.noinc.shared.b64 [%0];" :: "r"(mbar) : "memory");
}
__device__ __forceinline__ void mbar_init(uint32_t mbar, uint32_t cnt) {
    asm volatile("mbarrier.init.shared.b64 [%0], %1;" :: "r"(mbar), "r"(cnt) : "memory");
}
__device__ __forceinline__ void mbar_arrive(uint32_t mbar) {
    asm volatile("mbarrier.arrive.shared.b64 _, [%0];" :: "r"(mbar) : "memory");
}
__device__ __forceinline__ void mbar_wait(uint32_t mbar, uint32_t parity) {
    uint32_t done;
    asm volatile(
        "{\n\t.reg .pred p;\n\t"
        "mbarrier.try_wait.parity.acquire.cta.shared::cta.b64 p, [%1], %2;\n\t"
        "selp.b32 %0, 1, 0, p;\n\t}"
        : "=r"(done) : "r"(mbar), "r"(parity) : "memory");
    if (!done) {
        asm volatile(
            "{\n\t.reg .pred P1;\n\t"
            "WL_%=:\n\t"
            "mbarrier.try_wait.parity.acquire.cta.shared::cta.b64 P1, [%0], %1, 0x989680;\n\t"
            "@P1 bra.uni WD_%=;\n\t"
            "bra.uni WL_%=;\n\t"
            "WD_%=:\n\t}"
            :: "r"(mbar), "r"(parity) : "memory");
    }
}
__device__ __forceinline__ uint32_t smem_u32(const void* p) {
    uint32_t a;
    asm("{ .reg .u64 t; cvta.to.shared.u64 t, %1; cvt.u32.u64 %0, t; }" : "=r"(a) : "l"(p));
    return a;
}
__device__ __forceinline__ void ldsm_x4(uint32_t* r, uint32_t addr) {
    asm volatile("ldmatrix.sync.aligned.m8n8.x4.shared.b16 {%0,%1,%2,%3}, [%4];"
        : "=r"(r[0]), "=r"(r[1]), "=r"(r[2]), "=r"(r[3]) : "r"(addr));
}
__device__ __forceinline__ void mma_f16(float* c, const uint32_t* a, const uint32_t* b)
{
    asm volatile(
        "mma.sync.aligned.m16n8k16.row.col.f32.f16.f16.f32 "
        "{%0,%1,%2,%3}, {%4,%5,%6,%7}, {%8,%9}, {%0,%1,%2,%3};"
        : "+f"(c[0]), "+f"(c[1]), "+f"(c[2]), "+f"(c[3])
        : "r"(a[0]), "r"(a[1]), "r"(a[2]), "r"(a[3]), "r"(b[0]), "r"(b[1]));
}

#define SW128(off) ((off) ^ (((off) >> 3) & 0x70))

// ---------------- GEMM tiling (128x128x64, 3 stages, 2 CTAs/SM, 4 warps) --------------
#define BM 128
#define BN 128
#define BK 64                                   // 64 halfs = 128B rows
#define NSTAGE 3
#define A_BYTES (BM * 128)
#define STAGE_BYTES (BM * 128 + BN * 128)       // 32KB
#define SMEM_DYN (1024 + NSTAGE * STAGE_BYTES)  // 99328 -> 2 CTAs/SM
#define NTHREADS 128

// Strength-reduced stage fill (128 threads): per-thread chunk-0 bases precomputed;
// chunk t is a compile-time offset (+t*2048 smem = 16 rows, +t*16*GK halfs global).
__device__ __forceinline__ void fill_stage(uint32_t stage_base,
                                           const __half* aSrcT, const __half* bSrcT,
                                           uint32_t dOff, int k0)
{
#pragma unroll
    for (int t = 0; t < 8; t++)
        cp_async16(stage_base + dOff + t * 2048u, aSrcT + k0 + t * 16 * GK);
#pragma unroll
    for (int t = 0; t < 8; t++)
        cp_async16(stage_base + A_BYTES + dOff + t * 2048u, bSrcT + k0 + t * 16 * GK);
}

// ---------------- fp16 tensor-core GEMM: C[m,n] = sum_k A[m,k]*B[n,k] + bias[n] ----------
// mbarrier full/empty pipeline; warp grid 2x2, warp tile 64x64. K == GK (1024).
template <typename OutT>
__global__ __launch_bounds__(NTHREADS, 2)
void gemm_tc_f16(const __half* __restrict__ A,
                 const __half* __restrict__ B,
                 const float* __restrict__ bias,
                 OutT* __restrict__ C,
                 int M, int N)
{
    extern __shared__ char smem[];
    const uint32_t sbase = smem_u32(smem);
    const int tid = threadIdx.x;
    const int bm = blockIdx.y * BM;
    const int bn = blockIdx.x * BN;

    // control region: full[s] at +0,8,16 ; empty[s] at +24,32,40
    const uint32_t mb_full  = sbase;
    const uint32_t mb_empty = sbase + 24;

    const uint32_t tile0 = (sbase + 1023) & ~1023u;

    const int NT = GK / BK;   // 16

    // per-thread fill bases (chunk 0): row0 = tid>>3 (0..15), c4 = tid&7
    const __half* aSrcT = A + (size_t)(bm + (tid >> 3)) * GK + (tid & 7) * 8;
    const __half* bSrcT = B + (size_t)(bn + (tid >> 3)) * GK + (tid & 7) * 8;
    const uint32_t dOff = SW128((uint32_t)((tid >> 3) * 128 + (tid & 7) * 16));

    const int w = tid >> 5, lane = tid & 31;
    const int wm = (w >> 1) * 64;   // warp M offset (0 or 64)
    const int wn = (w & 1) * 64;    // warp N offset (0 or 64)

    // --- ldmatrix per-lane addressing (SW128 folded) ---
    const uint32_t a_row  = (uint32_t)(lane & 15);
    const uint32_t a_xor  = (uint32_t)((lane & 7) << 4);
    const uint32_t a_ch   = (uint32_t)((lane >> 4) * 16);
    const uint32_t b_row  = (uint32_t)((lane & 7) + ((lane >> 4) & 1) * 8);
    const uint32_t b_xor  = (uint32_t)((lane & 7) << 4);
    const uint32_t b_ch   = (uint32_t)(((lane >> 3) & 1) * 16);

    const uint32_t aBase = tile0 + (uint32_t)wm * 128 + a_row * 128;
    const uint32_t bBase = tile0 + (uint32_t)A_BYTES + (uint32_t)wn * 128 + b_row * 128;

    if (tid == 0) {
#pragma unroll
        for (int s = 0; s < NSTAGE; s++) {
            mbar_init(mb_full  + s * 8, NTHREADS);
            mbar_init(mb_empty + s * 8, NTHREADS);
        }
    }
    __syncthreads();

    float acc[4][8][4];
#pragma unroll
    for (int a = 0; a < 4; a++)
#pragma unroll
        for (int b = 0; b < 8; b++)
#pragma unroll
            for (int c = 0; c < 4; c++) acc[a][b][c] = 0.0f;

    // prologue: fill all 3 stages (tiles 0..2); one cp-gated arrive per stage
#pragma unroll
    for (int p = 0; p < NSTAGE; p++) {
        fill_stage(tile0 + p * STAGE_BYTES, aSrcT, bSrcT, dOff, p * BK);
        cp_async_mbar_arrive(mb_full + p * 8);
    }

    int s = 0, ph = 0;
    for (int i = 0; i < NT; i++) {
        const uint32_t soff = (uint32_t)s * STAGE_BYTES;

        // consumer: wait for tile i's data
        mbar_wait(mb_full + s * 8, (uint32_t)ph);

        const uint32_t aS = aBase + soff;
        const uint32_t bS = bBase + soff;

        // compute tile i: 4 k16-steps; signal stage-empty right after the LAST LDSM
#pragma unroll
        for (int ks = 0; ks < 4; ks++) {
            const uint32_t kb = (uint32_t)(ks * 32);
            const uint32_t ca = (kb + a_ch) ^ a_xor;
            const uint32_t cb = (kb + b_ch) ^ b_xor;
            uint32_t afr[4][4], bfr[16];
#pragma unroll
            for (int mt = 0; mt < 4; mt++) ldsm_x4(afr[mt], aS + mt * 2048 + ca);
#pragma unroll
            for (int j = 0; j < 4; j++)  ldsm_x4(&bfr[j * 4], bS + j * 2048 + cb);
            if (ks == 3) mbar_arrive(mb_empty + s * 8);   // done reading stage s
#pragma unroll
            for (int mt = 0; mt < 4; mt++)
#pragma unroll
                for (int nt = 0; nt < 8; nt++)
                    mma_f16(acc[mt][nt], afr[mt], &bfr[nt * 2]);
        }

        // producer: refill stage s with tile i+3 once everyone is done reading it
        if (i + NSTAGE < NT) {
            mbar_wait(mb_empty + s * 8, (uint32_t)ph);
            fill_stage(tile0 + soff, aSrcT, bSrcT, dOff, (i + NSTAGE) * BK);
            cp_async_mbar_arrive(mb_full + s * 8);
        }

        s++; if (s >= NSTAGE) { s = 0; ph ^= 1; }
    }

    // epilogue: bias + store (fp32 or half per OutT)
#pragma unroll
    for (int mt = 0; mt < 4; mt++) {
#pragma unroll
        for (int nt = 0; nt < 8; nt++) {
            int row0 = bm + wm + mt * 16 + (lane >> 2);
            int col0 = bn + wn + nt * 8 + (lane & 3) * 2;
            float b0 = __ldg(bias + col0), b1 = __ldg(bias + col0 + 1);
            float v00 = acc[mt][nt][0] + b0, v01 = acc[mt][nt][1] + b1;
            float v10 = acc[mt][nt][2] + b0, v11 = acc[mt][nt][3] + b1;
            if (sizeof(OutT) == 4) {
                float* Cf = (float*)C;
                *(float2*)(Cf + (size_t)row0 * N + col0) = make_float2(v00, v01);
                *(float2*)(Cf + (size_t)(row0 + 8) * N + col0) = make_float2(v10, v11);
            } else {
                __half* Ch = (__half*)C;
                *(__half2*)(Ch + (size_t)row0 * N + col0) = __floats2half2_rn(v00, v01);
                *(__half2*)(Ch + (size_t)(row0 + 8) * N + col0) = __floats2half2_rn(v10, v11);
            }
        }
    }
}

// ---------------- merged elementwise fp32 -> half (x ‖ Win ‖ Wout in one launch) -------
#define N4_X  (MTOT * DIM / 4)            // 8388608
#define N4_WI (3 * DIM * DIM / 4)         // 786432
#define N4_WO (DIM * DIM / 4)             // 262144
#define N4_TOT (N4_X + N4_WI + N4_WO)

__global__ __launch_bounds__(256)
void cvt_f16_all(const float* __restrict__ x,  __half* __restrict__ xh,
                 const float* __restrict__ wi, __half* __restrict__ wih,
                 const float* __restrict__ wo, __half* __restrict__ woh)
{
    int i = blockIdx.x * blockDim.x + threadIdx.x;
    if (i >= N4_TOT) return;
    const float* in;
    __half* out;
    int j;
    if (i < N4_X)              { in = x;  out = xh;  j = i; }
    else if (i < N4_X + N4_WI) { in = wi; out = wih; j = i - N4_X; }
    else                       { in = wo; out = woh; j = i - N4_X - N4_WI; }
    float4 v = reinterpret_cast<const float4*>(in)[j];
    __half2 pk[2] = { __floats2half2_rn(v.x, v.y), __floats2half2_rn(v.z, v.w) };
    reinterpret_cast<uint2*>(out)[j] = *reinterpret_cast<const uint2*>(pk);
}

// ---------------- gate + causal depthwise conv (K=3), half2, short chunks ----------------
#define LCHUNK 32
#define D2 (DIM / 2)          // 512 half2 channels
#define ROW2 (3 * DIM / 2)    // BCh row length in half2 units (1536)

__global__ __launch_bounds__(256)
void gate_conv_kernel(const __half2* __restrict__ BCx,
                      const float* __restrict__ wconv,
                      __half2* __restrict__ y)
{
    const int d2 = blockIdx.x * blockDim.x + threadIdx.x;   // 0..511
    const int b  = blockIdx.y;
    const int l0 = blockIdx.z * LCHUNK;

    const int c0 = 2 * d2, c1 = 2 * d2 + 1;
    const float2 w0 = make_float2(wconv[c0 * KCONV + 0], wconv[c1 * KCONV + 0]);
    const float2 w1 = make_float2(wconv[c0 * KCONV + 1], wconv[c1 * KCONV + 1]);
    const float2 w2 = make_float2(wconv[c0 * KCONV + 2], wconv[c1 * KCONV + 2]);

    const __half2* base = BCx + (size_t)b * SEQL * ROW2;

    float2 bxm2 = make_float2(0.f, 0.f), bxm1 = make_float2(0.f, 0.f);
    if (l0 >= 2) {
        const __half2* r = base + (size_t)(l0 - 2) * ROW2;
        float2 bg = __half22float2(r[d2]);
        float2 xg = __half22float2(r[2 * D2 + d2]);
        bxm2 = make_float2(bg.x * xg.x, bg.y * xg.y);
    }
    if (l0 >= 1) {
        const __half2* r = base + (size_t)(l0 - 1) * ROW2;
        float2 bg = __half22float2(r[d2]);
        float2 xg = __half22float2(r[2 * D2 + d2]);
        bxm1 = make_float2(bg.x * xg.x, bg.y * xg.y);
    }

#pragma unroll 4
    for (int l = l0; l < l0 + LCHUNK; l++) {
        const __half2* r = base + (size_t)l * ROW2;
        float2 bg = __half22float2(r[d2]);
        float2 cg = __half22float2(r[D2 + d2]);
        float2 xg = __half22float2(r[2 * D2 + d2]);
        float2 bx = make_float2(bg.x * xg.x, bg.y * xg.y);
        float cx = fmaf(w0.x, bxm2.x, fmaf(w1.x, bxm1.x, w2.x * bx.x));
        float cy = fmaf(w0.y, bxm2.y, fmaf(w1.y, bxm1.y, w2.y * bx.y));
        y[((size_t)b * SEQL + l) * D2 + d2] = __floats2half2_rn(cg.x * cx, cg.y * cy);
        bxm2 = bxm1;
        bxm1 = bx;
    }
}

// ---------------------------------------------------------------------------
extern "C" void kernel_launch(void* const* d_in, const int* in_sizes, int n_in,
                              void* d_out, int out_size)
{
    const float* x     = (const float*)d_in[0];
    const float* Win   = (const float*)d_in[1];
    const float* bin_  = (const float*)d_in[2];
    const float* wconv = (const float*)d_in[3];
    const float* Wout  = (const float*)d_in[4];
    const float* bout  = (const float*)d_in[5];
    float* out = (float*)d_out;

    __half *BCh, *yh, *xh, *Wih, *Woh;
    cudaGetSymbolAddress((void**)&BCh, g_BCh);
    cudaGetSymbolAddress((void**)&yh,  g_yh);
    cudaGetSymbolAddress((void**)&xh,  g_xh);
    cudaGetSymbolAddress((void**)&Wih, g_Wih);
    cudaGetSymbolAddress((void**)&Woh, g_Woh);

    cudaFuncSetAttribute(gemm_tc_f16<__half>, cudaFuncAttributeMaxDynamicSharedMemorySize, SMEM_DYN);
    cudaFuncSetAttribute(gemm_tc_f16<float>,  cudaFuncAttributeMaxDynamicSharedMemorySize, SMEM_DYN);

    const int M = MTOT;

    // convert inputs/weights to half (single merged launch)
    cvt_f16_all<<<(N4_TOT + 255) / 256, 256>>>(x, xh, Win, Wih, Wout, Woh);

    // GEMM 1: BCh = half(xh @ Wih^T + bin)   (M x 3072, K=1024)
    {
        dim3 grid((3 * DIM) / BN, M / BM);
        gemm_tc_f16<__half><<<grid, NTHREADS, SMEM_DYN>>>(xh, Wih, bin_, BCh, M, 3 * DIM);
    }

    // gate + causal conv -> yh (half2 vectorized, short chunks)
    {
        dim3 grid(D2 / 256, BATCH, SEQL / LCHUNK);
        gate_conv_kernel<<<grid, 256>>>((const __half2*)BCh, wconv, (__half2*)yh);
    }

    // GEMM 2: out = yh @ Woh^T + bout  (M x 1024, K=1024)
    {
        dim3 grid(DIM / BN, M / BM);
        gemm_tc_f16<float><<<grid, NTHREADS, SMEM_DYN>>>(yh, Woh, bout, out, M, DIM);
    }
}